// round 10
// baseline (speedup 1.0000x reference)
#include <cuda_runtime.h>
#include <cstdint>

#define NBLK 148
#define NTHR 512

// ---------------- static device scratch ----------------
__device__ __align__(16) float g_P[5767168];
__device__ __align__(16) float g_oatt[64 * 512];
__device__ __align__(16) float g_res1[64 * 512];
__device__ __align__(16) float g_part[64 * 8 * 512];
__device__ __align__(16) float g_wexp[64 * 1024];
__device__ __align__(16) float g_wchunk[1024];
// [0]=stealA, [8]=stealB, [32]=go word, flags at 64 + bid*32
__device__ unsigned g_sync[64 + 148 * 32];

// partial-region offsets (floats)
#define OFF_P1 0        // pre1:  ns=3,  ldp=512
#define OFF_P2 98304    // pre2:  ns=8,  ldp=256
#define OFF_A  229376   // gruA:  ns=12, ldp=1536
#define OFF_W  1409024  // wdec:  ns=8,  ldp=512
#define OFF_G  1671168  // wsc|g1:ns=18, ldp=2048
#define OFF_2  4030464  // g2:    ns=16, ldp=1536
#define OFF_O  5603328  // wout:  ns=16, ldp=160

__device__ __forceinline__ float tanh_fast(float x) {
    float y; asm("tanh.approx.f32 %0, %1;" : "=f"(y) : "f"(x)); return y;
}
__device__ __forceinline__ float gru_out(float gr, float gz, float gn,
                                         float br, float bz, float bn) {
    float r  = 1.f / (1.f + __expf(-(gr + br)));
    float z  = 1.f / (1.f + __expf(-(gz + bz)));
    float nn = tanhf(gn + r * bn);
    return (1.f - z) * nn;
}
__device__ __forceinline__ void add4(float4& a, const float4 b) {
    a.x += b.x; a.y += b.y; a.z += b.z; a.w += b.w;
}
__device__ __forceinline__ void bar_half(int half) {
    asm volatile("bar.sync %0, 256;" :: "r"(half + 1) : "memory");
}

// two-level grid barrier: per-CTA release flag; CTA0 aggregates -> go word;
// others poll go with nanosleep backoff (minimal L2 poll traffic).
__device__ __forceinline__ void gbar(unsigned ep) {
    __syncthreads();
    if (threadIdx.x == 0) {
        asm volatile("st.release.gpu.global.u32 [%0], %1;"
                     :: "l"(g_sync + 64 + blockIdx.x * 32), "r"(ep) : "memory");
    }
    if (blockIdx.x == 0) {
        if (threadIdx.x < 148) {
            const unsigned* p = g_sync + 64 + threadIdx.x * 32;
            unsigned v;
            do {
                asm volatile("ld.acquire.gpu.global.u32 %0, [%1];"
                             : "=r"(v) : "l"(p) : "memory");
            } while (v < ep);
        }
        __syncthreads();
        if (threadIdx.x == 0) {
            asm volatile("st.release.gpu.global.u32 [%0], %1;"
                         :: "l"(g_sync + 32), "r"(ep) : "memory");
        }
    } else if (threadIdx.x == 0) {
        unsigned v;
        for (;;) {
            asm volatile("ld.acquire.gpu.global.u32 %0, [%1];"
                         : "=r"(v) : "l"(g_sync + 32) : "memory");
            if (v >= ep) break;
            __nanosleep(128);
        }
    }
    __syncthreads();
}

// ---------------- X functors ----------------
struct XDirect {
    const float* X; int ldx;
    __device__ __forceinline__ float4 load4(int n, int k) const {
        return *reinterpret_cast<const float4*>(X + (size_t)n * ldx + k);
    }
    __device__ __forceinline__ float load1(int n, int k) const {
        return X[(size_t)n * ldx + k];
    }
};
struct XPre1Red {
    const float* P1; const float* pb1;
    __device__ __forceinline__ float4 load4(int n, int k) const {
        float4 s = *reinterpret_cast<const float4*>(pb1 + k);
#pragma unroll
        for (int sp = 0; sp < 3; sp++)
            add4(s, *reinterpret_cast<const float4*>(P1 + sp * 32768 + n * 512 + k));
        s.x = fmaxf(s.x, 0.f); s.y = fmaxf(s.y, 0.f);
        s.z = fmaxf(s.z, 0.f); s.w = fmaxf(s.w, 0.f);
        return s;
    }
    __device__ __forceinline__ float load1(int n, int k) const {
        float s = pb1[k];
        for (int sp = 0; sp < 3; sp++) s += P1[sp * 32768 + n * 512 + k];
        return fmaxf(s, 0.f);
    }
};
struct XPre2Red {
    const float* P2; const float* pb2; const float* sv;
    __device__ __forceinline__ float4 load4(int n, int k) const {
        if (k < 256) {
            float4 s = *reinterpret_cast<const float4*>(pb2 + k);
#pragma unroll
            for (int sp = 0; sp < 8; sp++)
                add4(s, *reinterpret_cast<const float4*>(P2 + sp * 16384 + n * 256 + k));
            s.x = fmaxf(s.x, 0.f); s.y = fmaxf(s.y, 0.f);
            s.z = fmaxf(s.z, 0.f); s.w = fmaxf(s.w, 0.f);
            return s;
        }
        return *reinterpret_cast<const float4*>(sv + n * 128 + (k - 256));
    }
    __device__ __forceinline__ float load1(int n, int k) const {
        if (k < 256) {
            float s = pb2[k];
            for (int sp = 0; sp < 8; sp++) s += P2[sp * 16384 + n * 256 + k];
            return fmaxf(s, 0.f);
        }
        return sv[n * 128 + (k - 256)];
    }
};
struct XGruARed {
    const float* P; const float* bih; const float* bhh;
    __device__ __forceinline__ float4 load4(int n, int k) const {
        const float* b = P + (size_t)n * 1536 + k;
        float4 r = *reinterpret_cast<const float4*>(bih + k);
        float4 z = *reinterpret_cast<const float4*>(bih + 512 + k);
        float4 m = *reinterpret_cast<const float4*>(bih + 1024 + k);
#pragma unroll
        for (int sp = 0; sp < 12; sp++) {
            const float* q = b + (size_t)sp * 98304;
            add4(r, *reinterpret_cast<const float4*>(q));
            add4(z, *reinterpret_cast<const float4*>(q + 512));
            add4(m, *reinterpret_cast<const float4*>(q + 1024));
        }
        float4 br = *reinterpret_cast<const float4*>(bhh + k);
        float4 bz = *reinterpret_cast<const float4*>(bhh + 512 + k);
        float4 bn = *reinterpret_cast<const float4*>(bhh + 1024 + k);
        float4 o;
        o.x = gru_out(r.x, z.x, m.x, br.x, bz.x, bn.x);
        o.y = gru_out(r.y, z.y, m.y, br.y, bz.y, bn.y);
        o.z = gru_out(r.z, z.z, m.z, br.z, bz.z, bn.z);
        o.w = gru_out(r.w, z.w, m.w, br.w, bz.w, bn.w);
        return o;
    }
    __device__ __forceinline__ float load1(int n, int k) const {
        float gr = bih[k], gz = bih[512 + k], gn = bih[1024 + k];
        for (int sp = 0; sp < 12; sp++) {
            const float* q = P + (size_t)sp * 98304 + (size_t)n * 1536 + k;
            gr += q[0]; gz += q[512]; gn += q[1024];
        }
        return gru_out(gr, gz, gn, bhh[k], bhh[512 + k], bhh[1024 + k]);
    }
};
struct XOdecRed {
    const float* part; const float* wchunk; const float* oatt; const float* sv;
    __device__ __forceinline__ float4 load4(int n, int k) const {
        if (k < 512) {
            float4 s = make_float4(0.f, 0.f, 0.f, 0.f);
#pragma unroll
            for (int sp = 0; sp < 8; sp++)
                add4(s, *reinterpret_cast<const float4*>(part + (size_t)(n * 8 + sp) * 512 + k));
            float w = 0.f;
#pragma unroll
            for (int sp = 0; sp < 16; sp++) w += wchunk[n * 16 + sp];
            float inv = 1.f / fmaxf(w, 1e-12f);
            s.x *= inv; s.y *= inv; s.z *= inv; s.w *= inv;
            return s;
        }
        if (k < 1024) return *reinterpret_cast<const float4*>(oatt + n * 512 + (k - 512));
        return *reinterpret_cast<const float4*>(sv + n * 128 + (k - 1024));
    }
    __device__ __forceinline__ float load1(int n, int k) const {
        if (k < 512) {
            float s = 0.f, w = 0.f;
            for (int sp = 0; sp < 8; sp++) s += part[(size_t)(n * 8 + sp) * 512 + k];
            for (int sp = 0; sp < 16; sp++) w += wchunk[n * 16 + sp];
            return s / fmaxf(w, 1e-12f);
        }
        if (k < 1024) return oatt[n * 512 + (k - 512)];
        return sv[n * 128 + (k - 1024)];
    }
};
struct XGru2Red {
    const float* P; const float* bih; const float* bhh; const float* res1;
    __device__ __forceinline__ float4 load4(int n, int k) const {
        const float* b = P + (size_t)n * 1536 + k;
        float4 r = *reinterpret_cast<const float4*>(bih + k);
        float4 z = *reinterpret_cast<const float4*>(bih + 512 + k);
        float4 m = *reinterpret_cast<const float4*>(bih + 1024 + k);
#pragma unroll
        for (int sp = 0; sp < 16; sp++) {
            const float* q = b + (size_t)sp * 98304;
            add4(r, *reinterpret_cast<const float4*>(q));
            add4(z, *reinterpret_cast<const float4*>(q + 512));
            add4(m, *reinterpret_cast<const float4*>(q + 1024));
        }
        float4 br = *reinterpret_cast<const float4*>(bhh + k);
        float4 bz = *reinterpret_cast<const float4*>(bhh + 512 + k);
        float4 bn = *reinterpret_cast<const float4*>(bhh + 1024 + k);
        float4 rv = *reinterpret_cast<const float4*>(res1 + n * 512 + k);
        float4 o;
        o.x = gru_out(r.x, z.x, m.x, br.x, bz.x, bn.x) + rv.x;
        o.y = gru_out(r.y, z.y, m.y, br.y, bz.y, bn.y) + rv.y;
        o.z = gru_out(r.z, z.z, m.z, br.z, bz.z, bn.z) + rv.z;
        o.w = gru_out(r.w, z.w, m.w, br.w, bz.w, bn.w) + rv.w;
        return o;
    }
    __device__ __forceinline__ float load1(int n, int k) const {
        float gr = bih[k], gz = bih[512 + k], gn = bih[1024 + k];
        for (int sp = 0; sp < 16; sp++) {
            const float* q = P + (size_t)sp * 98304 + (size_t)n * 1536 + k;
            gr += q[0]; gz += q[512]; gn += q[1024];
        }
        return gru_out(gr, gz, gn, bhh[k], bhh[512 + k], bhh[1024 + k]) + res1[n * 512 + k];
    }
};

// ---------------- dual-worker k-split GEMM stage ----------------
template <int KC, class XF>
__device__ __forceinline__ void gemm_stage(
    const XF xf,
    const float* __restrict__ W1, int m1, const float* __restrict__ W2, int ldw,
    int kjump_at, int kjump_ofs,
    int M, int K, int jt_n, int ks_n,
    float* __restrict__ P, int ldp, float* __restrict__ smh, int half, int htid)
{
    constexpr int K4 = KC / 4;
    constexpr int SH = (KC == 64) ? 4 : 3;
    float* xs = smh;            // [KC][68]
    float* ws = smh + KC * 68;  // [KC][132]
    const int items = jt_n * ks_n;

    for (int it = blockIdx.x * 2 + half; it < items; it += 2 * NBLK) {
        const int ksp = it / jt_n;
        const int jt  = it - ksp * jt_n;
        const int j0  = jt << 7;
        const int k0  = ksp * KC;
        for (int idx = htid; idx < K4 * 64; idx += 256) {
            int k4 = idx & (K4 - 1), n = idx >> SH;
            int kk = k0 + (k4 << 2);
            float4 v = make_float4(0.f, 0.f, 0.f, 0.f);
            if (kk + 3 < K) v = xf.load4(n, kk);
            else {
                if (kk + 0 < K) v.x = xf.load1(n, kk + 0);
                if (kk + 1 < K) v.y = xf.load1(n, kk + 1);
                if (kk + 2 < K) v.z = xf.load1(n, kk + 2);
                if (kk + 3 < K) v.w = xf.load1(n, kk + 3);
            }
            float* d = xs + (k4 << 2) * 68 + n;
            d[0] = v.x; d[68] = v.y; d[136] = v.z; d[204] = v.w;
        }
        const int wofs = k0 + (k0 >= kjump_at ? kjump_ofs : 0);
        for (int idx = htid; idx < K4 * 128; idx += 256) {
            int k4 = idx & (K4 - 1), j = idx >> SH;
            int jr = j0 + j;
            float4 v = make_float4(0.f, 0.f, 0.f, 0.f);
            if (jr < M) {
                const float* Wr = (jr < m1) ? (W1 + (size_t)jr * ldw)
                                            : (W2 + (size_t)(jr - m1) * ldw);
                int kk = k0 + (k4 << 2);
                if (kk + 3 < K) v = *reinterpret_cast<const float4*>(Wr + wofs + (k4 << 2));
                else {
                    if (kk + 0 < K) v.x = Wr[wofs + (k4 << 2) + 0];
                    if (kk + 1 < K) v.y = Wr[wofs + (k4 << 2) + 1];
                    if (kk + 2 < K) v.z = Wr[wofs + (k4 << 2) + 2];
                    if (kk + 3 < K) v.w = Wr[wofs + (k4 << 2) + 3];
                }
            }
            float* d = ws + (k4 << 2) * 132 + j;
            d[0] = v.x; d[132] = v.y; d[264] = v.z; d[396] = v.w;
        }
        bar_half(half);

        const int tj = htid & 31, tn = htid >> 5;
        float acc[4][8];
#pragma unroll
        for (int a = 0; a < 4; a++)
#pragma unroll
            for (int b = 0; b < 8; b++) acc[a][b] = 0.f;

#pragma unroll 8
        for (int k = 0; k < KC; k++) {
            float4 wv = *reinterpret_cast<const float4*>(ws + k * 132 + tj * 4);
            float4 xa = *reinterpret_cast<const float4*>(xs + k * 68 + tn * 8);
            float4 xb = *reinterpret_cast<const float4*>(xs + k * 68 + tn * 8 + 4);
            float xv[8] = {xa.x, xa.y, xa.z, xa.w, xb.x, xb.y, xb.z, xb.w};
            float wr[4] = {wv.x, wv.y, wv.z, wv.w};
#pragma unroll
            for (int jj = 0; jj < 4; jj++)
#pragma unroll
                for (int i = 0; i < 8; i++) acc[jj][i] += wr[jj] * xv[i];
        }

        if (j0 + tj * 4 < M) {
            float* base = P + (size_t)ksp * (64 * ldp) + j0 + tj * 4;
#pragma unroll
            for (int i = 0; i < 8; i++) {
                int n = tn * 8 + i;
                *reinterpret_cast<float4*>(base + (size_t)n * ldp) =
                    make_float4(acc[0][i], acc[1][i], acc[2][i], acc[3][i]);
            }
        }
        bar_half(half);
    }
}

// ---------------- attention phase A: warp-stealing score chunks ----------------
// item = (n, 64-row chunk): 1024 items, grabbed 2 at a time per warp.
__device__ void attnA(const float* __restrict__ encW, const float* __restrict__ wattn,
                      const float* __restrict__ battn, const float* __restrict__ bdec,
                      const int* __restrict__ len)
{
    const int lane = threadIdx.x & 31;
    const float bat = battn[0];
    for (;;) {
        int base;
        if (lane == 0) base = (int)atomicAdd(&g_sync[0], 2u);
        base = __shfl_sync(0xffffffffu, base, 0);
        if (base >= 1024) break;
        const int iend = min(base + 2, 1024);
        for (int id = base; id < iend; id++) {
            const int n = id >> 4, t0 = (id & 15) << 6;
            const int L = len[n];
            const int rows = min(64, L - t0);
            if (rows <= 0) {
                if (lane == 0) g_wchunk[id] = 0.f;
                continue;
            }
            float4 awr[4], wvr[4];
#pragma unroll
            for (int q = 0; q < 4; q++) {
                int c = lane * 4 + q * 128;
                float4 s = *reinterpret_cast<const float4*>(bdec + c);
#pragma unroll
                for (int sp = 0; sp < 8; sp++)
                    add4(s, *reinterpret_cast<const float4*>(g_P + OFF_W + sp * 32768 + n * 512 + c));
                awr[q] = s;
                wvr[q] = *reinterpret_cast<const float4*>(wattn + c);
            }
            const float* rbase = encW + ((size_t)(n << 10) + t0) * 512;
            float* weo = g_wexp + (n << 10) + t0;
            float wsum = 0.f;

            for (int rr = 0; rr < rows; rr += 8) {
                float s[8];
#pragma unroll
                for (int i = 0; i < 8; i++) {
                    int r = rr + i;
                    float si = 0.f;
                    if (r < rows) {
                        const float* rp = rbase + (size_t)r * 512;
#pragma unroll
                        for (int q = 0; q < 4; q++) {
                            float4 v = *reinterpret_cast<const float4*>(rp + lane * 4 + q * 128);
                            si += tanh_fast(v.x + awr[q].x) * wvr[q].x
                                + tanh_fast(v.y + awr[q].y) * wvr[q].y
                                + tanh_fast(v.z + awr[q].z) * wvr[q].z
                                + tanh_fast(v.w + awr[q].w) * wvr[q].w;
                        }
                    }
                    s[i] = si;
                }
#pragma unroll
                for (int o = 16; o > 0; o >>= 1) {
#pragma unroll
                    for (int i = 0; i < 8; i++)
                        s[i] += __shfl_xor_sync(0xffffffffu, s[i], o);
                }
                if (lane == 0) {
#pragma unroll
                    for (int i = 0; i < 8; i++) {
                        int r = rr + i;
                        if (r < rows) {
                            float w = __expf(s[i] + bat);
                            weo[r] = w;
                            wsum += w;
                        }
                    }
                }
            }
            if (lane == 0) g_wchunk[id] = wsum;
        }
    }
}

// ---------------- attention phase B: warp-stealing column streams ----------------
// item = (n, colblock of 128, rowblock of 128): 2048 items, grabbed 4 at a time.
__device__ void attnB(const float* __restrict__ enc, const int* __restrict__ len)
{
    const int lane = threadIdx.x & 31;
    for (;;) {
        int base;
        if (lane == 0) base = (int)atomicAdd(&g_sync[8], 4u);
        base = __shfl_sync(0xffffffffu, base, 0);
        if (base >= 2048) break;
        const int iend = min(base + 4, 2048);
        for (int id = base; id < iend; id++) {
            const int n = id >> 5, cb = (id >> 3) & 3, rb = id & 7;
            const int col = cb * 128 + lane * 4;
            const int t0 = rb << 7;
            const int L = len[n];
            const int rows = min(128, L - t0);
            float4 acc = make_float4(0.f, 0.f, 0.f, 0.f);
            if (rows > 0) {
                const float* bp = enc + ((size_t)(n << 10) + t0) * 512 + col;
                const float* wp = g_wexp + (n << 10) + t0;
                int r = 0;
                for (; r + 8 <= rows; r += 8) {
                    float w[8]; float4 v[8];
#pragma unroll
                    for (int i = 0; i < 8; i++) {
                        w[i] = wp[r + i];
                        v[i] = *reinterpret_cast<const float4*>(bp + (size_t)(r + i) * 512);
                    }
#pragma unroll
                    for (int i = 0; i < 8; i++) {
                        acc.x += w[i] * v[i].x; acc.y += w[i] * v[i].y;
                        acc.z += w[i] * v[i].z; acc.w += w[i] * v[i].w;
                    }
                }
                for (; r < rows; r++) {
                    float w = wp[r];
                    float4 v = *reinterpret_cast<const float4*>(bp + (size_t)r * 512);
                    acc.x += w * v.x; acc.y += w * v.y; acc.z += w * v.z; acc.w += w * v.w;
                }
            }
            *reinterpret_cast<float4*>(g_part + (size_t)(n * 8 + rb) * 512 + col) = acc;
        }
    }
}

// ---------------- the mega kernel ----------------
struct MArgs {
    const float *enc, *encW, *dec, *sv;
    const int* len;
    const float *pw1, *pb1, *pw2, *pb2, *wdec_, *bdec;
    const float *ga_ih, *ga_bih, *ga_bhh, *wattn, *battn;
    const float *wsc, *bsc, *g1_ih, *g1_bih, *g1_bhh;
    const float *g2_ih, *g2_bih, *g2_bhh, *wout_, *bout;
    float* out;
};

__global__ __launch_bounds__(NTHR) void mega(MArgs a)
{
    extern __shared__ float sm[];
    const int tid  = threadIdx.x;
    const int half = tid >> 8;
    const int htid = tid & 255;
    float* smh = sm + half * 12800;
    const int BIGJ = 1 << 30;

    // S1: pre1 partials (M=512,K=80,KC=32,jt=4,ks=3)
    gemm_stage<32>(XDirect{a.dec, 80}, a.pw1, BIGJ, a.pw1, 80, BIGJ, 0,
                   512, 80, 4, 3, g_P + OFF_P1, 512, smh, half, htid);
    gbar(1);

    // S2: pre2 partials (M=256,K=512,KC=64,jt=2,ks=8); X = relu(pre1-reduce)
    gemm_stage<64>(XPre1Red{g_P + OFF_P1, a.pb1}, a.pw2, BIGJ, a.pw2, 512, BIGJ, 0,
                   256, 512, 2, 8, g_P + OFF_P2, 256, smh, half, htid);
    gbar(2);

    // S4: gruA input GEMM (M=1536,K=384,KC=32,jt=12,ks=12), W col jump at 256 (+512)
    gemm_stage<32>(XPre2Red{g_P + OFF_P2, a.pb2, a.sv}, a.ga_ih, BIGJ, a.ga_ih, 896,
                   256, 512, 1536, 384, 12, 12, g_P + OFF_A, 1536, smh, half, htid);
    gbar(3);

    // S6: wdec partials (M=512,K=512,KC=64,jt=4,ks=8); X = gruA reduce on the fly.
    {
        XGruARed xga{g_P + OFF_A, a.ga_bih, a.ga_bhh};
        for (int idx = blockIdx.x * NTHR + tid; idx < 64 * 128; idx += NBLK * NTHR) {
            int n = idx >> 7, c = (idx & 127) << 2;
            *reinterpret_cast<float4*>(g_oatt + n * 512 + c) = xga.load4(n, c);
        }
        gemm_stage<64>(xga, a.wdec_, BIGJ, a.wdec_, 512, BIGJ, 0,
                       512, 512, 4, 8, g_P + OFF_W, 512, smh, half, htid);
    }
    gbar(4);

    // S8a: scores — warp-stealing; attW slice built from partials in-warp
    attnA(a.encW, a.wattn, a.battn, a.bdec, a.len);
    gbar(5);

    // S8b: weighted column sums — warp-stealing
    attnB(a.enc, a.len);
    gbar(6);

    // S10: fused wsc|g1 GEMM (M=2048,K=1152,KC=64,jt=16,ks=18); X = out_dec on the fly.
    {
        XOdecRed xod{g_part, g_wchunk, g_oatt, a.sv};
        for (int idx = blockIdx.x * NTHR + tid; idx < 64 * 128; idx += NBLK * NTHR) {
            int n = idx >> 7, c = (idx & 127) << 2;
            *reinterpret_cast<float4*>(a.out + 10240 + (size_t)n * 512 + c) = xod.load4(n, c);
        }
        gemm_stage<64>(xod, a.wsc, 512, a.g1_ih, 1152, BIGJ, 0,
                       2048, 1152, 16, 18, g_P + OFF_G, 2048, smh, half, htid);
    }
    gbar(7);

    // S11: residual = sc + gru1 -> res1
    for (int idx = blockIdx.x * NTHR + tid; idx < 64 * 512; idx += NBLK * NTHR) {
        int n = idx >> 9, j = idx & 511;
        float sc = a.bsc[j], gr = a.g1_bih[j], gz = a.g1_bih[512 + j], gn = a.g1_bih[1024 + j];
        for (int s = 0; s < 18; s++) {
            const float* pp = g_P + OFF_G + (size_t)s * 131072 + (size_t)n * 2048;
            sc += pp[j]; gr += pp[512 + j]; gz += pp[1024 + j]; gn += pp[1536 + j];
        }
        g_res1[idx] = sc + gru_out(gr, gz, gn, a.g1_bhh[j], a.g1_bhh[512 + j], a.g1_bhh[1024 + j]);
    }
    gbar(8);

    // S12: g2 GEMM (M=1536,K=512,KC=32,jt=12,ks=16)
    gemm_stage<32>(XDirect{g_res1, 512}, a.g2_ih, BIGJ, a.g2_ih, 512, BIGJ, 0,
                   1536, 512, 12, 16, g_P + OFF_2, 1536, smh, half, htid);
    gbar(9);

    // S14: wout GEMM (M=160,K=512,KC=32,jt=2,ks=16); X = res1 + gru2 reduce on the fly
    gemm_stage<32>(XGru2Red{g_P + OFF_2, a.g2_bih, a.g2_bhh, g_res1},
                   a.wout_, BIGJ, a.wout_, 512, BIGJ, 0,
                   160, 512, 2, 16, g_P + OFF_O, 160, smh, half, htid);
    gbar(10);

    // S15: wout reduce -> d_out[0:10240]
    for (int idx = blockIdx.x * NTHR + tid; idx < 64 * 160; idx += NBLK * NTHR) {
        int n = idx / 160, j = idx - n * 160;
        float s = a.bout[j];
#pragma unroll
        for (int sp = 0; sp < 16; sp++) s += g_P[OFF_O + sp * 10240 + n * 160 + j];
        a.out[idx] = s;
    }
}

// ---------------- host orchestration ----------------
extern "C" void kernel_launch(void* const* d_in, const int* in_sizes, int n_in,
                              void* d_out, int out_size)
{
    (void)n_in; (void)out_size;
    bool dictord = (in_sizes[4] == 64);
    int b = dictord ? 5 : 4;

    MArgs a;
    a.enc   = (const float*)d_in[0];
    a.encW  = (const float*)d_in[1];
    a.dec   = (const float*)d_in[2];
    a.sv    = (const float*)d_in[3];
    a.len   = (const int*)(dictord ? d_in[4] : d_in[28]);
    a.pw1   = (const float*)d_in[b + 0];
    a.pb1   = (const float*)d_in[b + 1];
    a.pw2   = (const float*)d_in[b + 2];
    a.pb2   = (const float*)d_in[b + 3];
    a.wdec_ = (const float*)d_in[b + 4];
    a.bdec  = (const float*)d_in[b + 5];
    a.ga_ih = (const float*)d_in[b + 6];
    a.ga_bih= (const float*)d_in[b + 8];
    a.ga_bhh= (const float*)d_in[b + 9];
    a.wattn = (const float*)d_in[b + 10];
    a.battn = (const float*)d_in[b + 11];
    a.wsc   = (const float*)d_in[b + 12];
    a.bsc   = (const float*)d_in[b + 13];
    a.g1_ih = (const float*)d_in[b + 14];
    a.g1_bih= (const float*)d_in[b + 16];
    a.g1_bhh= (const float*)d_in[b + 17];
    a.g2_ih = (const float*)d_in[b + 18];
    a.g2_bih= (const float*)d_in[b + 20];
    a.g2_bhh= (const float*)d_in[b + 21];
    a.wout_ = (const float*)d_in[b + 22];
    a.bout  = (const float*)d_in[b + 23];
    a.out   = (float*)d_out;

    static bool attr_set = false;
    if (!attr_set) {
        cudaFuncSetAttribute(mega, cudaFuncAttributeMaxDynamicSharedMemorySize, 102400);
        attr_set = true;
    }

    void* sync;
    cudaGetSymbolAddress(&sync, g_sync);
    cudaMemsetAsync(sync, 0, (64 + 148 * 32) * sizeof(unsigned));

    mega<<<NBLK, NTHR, 102400>>>(a);
}

// round 11
// speedup vs baseline: 1.8637x; 1.8637x over previous
#include <cuda_runtime.h>
#include <cstdint>

#define NBLK 148
#define NTHR 512

// ---------------- static device scratch ----------------
__device__ __align__(16) float g_P[5767168];
__device__ __align__(16) float g_oatt[64 * 512];
__device__ __align__(16) float g_res1[64 * 512];
__device__ __align__(16) float g_part[64 * 8 * 512];
__device__ __align__(16) float g_wexp[64 * 1024];
__device__ __align__(16) float g_wchunk[1024];
__device__ unsigned g_sync[32];   // [0] = barrier counter; memset per launch

// partial-region offsets (floats)
#define OFF_P1 0        // pre1:  ns=3,  ldp=512
#define OFF_P2 98304    // pre2:  ns=8,  ldp=256
#define OFF_A  229376   // gruA:  ns=12, ldp=1536
#define OFF_W  1409024  // wdec:  ns=8,  ldp=512
#define OFF_G  1671168  // wsc|g1:ns=18, ldp=2048
#define OFF_2  4030464  // g2:    ns=16, ldp=1536
#define OFF_O  5603328  // wout:  ns=16, ldp=160

__device__ __forceinline__ float tanh_fast(float x) {
    float y; asm("tanh.approx.f32 %0, %1;" : "=f"(y) : "f"(x)); return y;
}
__device__ __forceinline__ float gru_out(float gr, float gz, float gn,
                                         float br, float bz, float bn) {
    float r  = 1.f / (1.f + __expf(-(gr + br)));
    float z  = 1.f / (1.f + __expf(-(gz + bz)));
    float nn = tanhf(gn + r * bn);
    return (1.f - z) * nn;
}
__device__ __forceinline__ void add4(float4& a, const float4 b) {
    a.x += b.x; a.y += b.y; a.z += b.z; a.w += b.w;
}
__device__ __forceinline__ void bar_half(int half) {
    asm volatile("bar.sync %0, 256;" :: "r"(half + 1) : "memory");
}

// R4-proven grid barrier: single counter, ONE poller per CTA (thread 0).
__device__ __forceinline__ void gbar(unsigned target) {
    __syncthreads();
    if (threadIdx.x == 0) {
        __threadfence();
        asm volatile("red.release.gpu.global.add.u32 [%0], %1;"
                     :: "l"(&g_sync[0]), "r"(1u) : "memory");
        unsigned v;
        do {
            asm volatile("ld.acquire.gpu.global.u32 %0, [%1];"
                         : "=r"(v) : "l"(&g_sync[0]) : "memory");
        } while (v < target);
    }
    __syncthreads();
}

// ---------------- X functors ----------------
struct XDirect {
    const float* X; int ldx;
    __device__ __forceinline__ float4 load4(int n, int k) const {
        return *reinterpret_cast<const float4*>(X + (size_t)n * ldx + k);
    }
    __device__ __forceinline__ float load1(int n, int k) const {
        return X[(size_t)n * ldx + k];
    }
};
struct XPre1Red {
    const float* P1; const float* pb1;
    __device__ __forceinline__ float4 load4(int n, int k) const {
        float4 s = *reinterpret_cast<const float4*>(pb1 + k);
#pragma unroll
        for (int sp = 0; sp < 3; sp++)
            add4(s, *reinterpret_cast<const float4*>(P1 + sp * 32768 + n * 512 + k));
        s.x = fmaxf(s.x, 0.f); s.y = fmaxf(s.y, 0.f);
        s.z = fmaxf(s.z, 0.f); s.w = fmaxf(s.w, 0.f);
        return s;
    }
    __device__ __forceinline__ float load1(int n, int k) const {
        float s = pb1[k];
        for (int sp = 0; sp < 3; sp++) s += P1[sp * 32768 + n * 512 + k];
        return fmaxf(s, 0.f);
    }
};
struct XPre2Red {
    const float* P2; const float* pb2; const float* sv;
    __device__ __forceinline__ float4 load4(int n, int k) const {
        if (k < 256) {
            float4 s = *reinterpret_cast<const float4*>(pb2 + k);
#pragma unroll
            for (int sp = 0; sp < 8; sp++)
                add4(s, *reinterpret_cast<const float4*>(P2 + sp * 16384 + n * 256 + k));
            s.x = fmaxf(s.x, 0.f); s.y = fmaxf(s.y, 0.f);
            s.z = fmaxf(s.z, 0.f); s.w = fmaxf(s.w, 0.f);
            return s;
        }
        return *reinterpret_cast<const float4*>(sv + n * 128 + (k - 256));
    }
    __device__ __forceinline__ float load1(int n, int k) const {
        if (k < 256) {
            float s = pb2[k];
            for (int sp = 0; sp < 8; sp++) s += P2[sp * 16384 + n * 256 + k];
            return fmaxf(s, 0.f);
        }
        return sv[n * 128 + (k - 256)];
    }
};
struct XGruARed {
    const float* P; const float* bih; const float* bhh;
    __device__ __forceinline__ float4 load4(int n, int k) const {
        const float* b = P + (size_t)n * 1536 + k;
        float4 r = *reinterpret_cast<const float4*>(bih + k);
        float4 z = *reinterpret_cast<const float4*>(bih + 512 + k);
        float4 m = *reinterpret_cast<const float4*>(bih + 1024 + k);
#pragma unroll
        for (int sp = 0; sp < 12; sp++) {
            const float* q = b + (size_t)sp * 98304;
            add4(r, *reinterpret_cast<const float4*>(q));
            add4(z, *reinterpret_cast<const float4*>(q + 512));
            add4(m, *reinterpret_cast<const float4*>(q + 1024));
        }
        float4 br = *reinterpret_cast<const float4*>(bhh + k);
        float4 bz = *reinterpret_cast<const float4*>(bhh + 512 + k);
        float4 bn = *reinterpret_cast<const float4*>(bhh + 1024 + k);
        float4 o;
        o.x = gru_out(r.x, z.x, m.x, br.x, bz.x, bn.x);
        o.y = gru_out(r.y, z.y, m.y, br.y, bz.y, bn.y);
        o.z = gru_out(r.z, z.z, m.z, br.z, bz.z, bn.z);
        o.w = gru_out(r.w, z.w, m.w, br.w, bz.w, bn.w);
        return o;
    }
    __device__ __forceinline__ float load1(int n, int k) const {
        float gr = bih[k], gz = bih[512 + k], gn = bih[1024 + k];
        for (int sp = 0; sp < 12; sp++) {
            const float* q = P + (size_t)sp * 98304 + (size_t)n * 1536 + k;
            gr += q[0]; gz += q[512]; gn += q[1024];
        }
        return gru_out(gr, gz, gn, bhh[k], bhh[512 + k], bhh[1024 + k]);
    }
};
struct XOdecRed {
    const float* part; const float* wchunk; const float* oatt; const float* sv;
    __device__ __forceinline__ float4 load4(int n, int k) const {
        if (k < 512) {
            float4 s = make_float4(0.f, 0.f, 0.f, 0.f);
#pragma unroll
            for (int sp = 0; sp < 8; sp++)
                add4(s, *reinterpret_cast<const float4*>(part + (size_t)(n * 8 + sp) * 512 + k));
            float w = 0.f;
#pragma unroll
            for (int sp = 0; sp < 16; sp++) w += wchunk[n * 16 + sp];
            float inv = 1.f / fmaxf(w, 1e-12f);
            s.x *= inv; s.y *= inv; s.z *= inv; s.w *= inv;
            return s;
        }
        if (k < 1024) return *reinterpret_cast<const float4*>(oatt + n * 512 + (k - 512));
        return *reinterpret_cast<const float4*>(sv + n * 128 + (k - 1024));
    }
    __device__ __forceinline__ float load1(int n, int k) const {
        if (k < 512) {
            float s = 0.f, w = 0.f;
            for (int sp = 0; sp < 8; sp++) s += part[(size_t)(n * 8 + sp) * 512 + k];
            for (int sp = 0; sp < 16; sp++) w += wchunk[n * 16 + sp];
            return s / fmaxf(w, 1e-12f);
        }
        if (k < 1024) return oatt[n * 512 + (k - 512)];
        return sv[n * 128 + (k - 1024)];
    }
};
struct XGru2Red {
    const float* P; const float* bih; const float* bhh; const float* res1;
    __device__ __forceinline__ float4 load4(int n, int k) const {
        const float* b = P + (size_t)n * 1536 + k;
        float4 r = *reinterpret_cast<const float4*>(bih + k);
        float4 z = *reinterpret_cast<const float4*>(bih + 512 + k);
        float4 m = *reinterpret_cast<const float4*>(bih + 1024 + k);
#pragma unroll
        for (int sp = 0; sp < 16; sp++) {
            const float* q = b + (size_t)sp * 98304;
            add4(r, *reinterpret_cast<const float4*>(q));
            add4(z, *reinterpret_cast<const float4*>(q + 512));
            add4(m, *reinterpret_cast<const float4*>(q + 1024));
        }
        float4 br = *reinterpret_cast<const float4*>(bhh + k);
        float4 bz = *reinterpret_cast<const float4*>(bhh + 512 + k);
        float4 bn = *reinterpret_cast<const float4*>(bhh + 1024 + k);
        float4 rv = *reinterpret_cast<const float4*>(res1 + n * 512 + k);
        float4 o;
        o.x = gru_out(r.x, z.x, m.x, br.x, bz.x, bn.x) + rv.x;
        o.y = gru_out(r.y, z.y, m.y, br.y, bz.y, bn.y) + rv.y;
        o.z = gru_out(r.z, z.z, m.z, br.z, bz.z, bn.z) + rv.z;
        o.w = gru_out(r.w, z.w, m.w, br.w, bz.w, bn.w) + rv.w;
        return o;
    }
    __device__ __forceinline__ float load1(int n, int k) const {
        float gr = bih[k], gz = bih[512 + k], gn = bih[1024 + k];
        for (int sp = 0; sp < 16; sp++) {
            const float* q = P + (size_t)sp * 98304 + (size_t)n * 1536 + k;
            gr += q[0]; gz += q[512]; gn += q[1024];
        }
        return gru_out(gr, gz, gn, bhh[k], bhh[512 + k], bhh[1024 + k]) + res1[n * 512 + k];
    }
};

// ---------------- dual-worker k-split GEMM stage ----------------
template <int KC, class XF>
__device__ __forceinline__ void gemm_stage(
    const XF xf,
    const float* __restrict__ W1, int m1, const float* __restrict__ W2, int ldw,
    int kjump_at, int kjump_ofs,
    int M, int K, int jt_n, int ks_n,
    float* __restrict__ P, int ldp, float* __restrict__ smh, int half, int htid)
{
    constexpr int K4 = KC / 4;
    constexpr int SH = (KC == 64) ? 4 : 3;
    float* xs = smh;            // [KC][68]
    float* ws = smh + KC * 68;  // [KC][132]
    const int items = jt_n * ks_n;

    for (int it = blockIdx.x * 2 + half; it < items; it += 2 * NBLK) {
        const int ksp = it / jt_n;
        const int jt  = it - ksp * jt_n;
        const int j0  = jt << 7;
        const int k0  = ksp * KC;
        for (int idx = htid; idx < K4 * 64; idx += 256) {
            int k4 = idx & (K4 - 1), n = idx >> SH;
            int kk = k0 + (k4 << 2);
            float4 v = make_float4(0.f, 0.f, 0.f, 0.f);
            if (kk + 3 < K) v = xf.load4(n, kk);
            else {
                if (kk + 0 < K) v.x = xf.load1(n, kk + 0);
                if (kk + 1 < K) v.y = xf.load1(n, kk + 1);
                if (kk + 2 < K) v.z = xf.load1(n, kk + 2);
                if (kk + 3 < K) v.w = xf.load1(n, kk + 3);
            }
            float* d = xs + (k4 << 2) * 68 + n;
            d[0] = v.x; d[68] = v.y; d[136] = v.z; d[204] = v.w;
        }
        const int wofs = k0 + (k0 >= kjump_at ? kjump_ofs : 0);
        for (int idx = htid; idx < K4 * 128; idx += 256) {
            int k4 = idx & (K4 - 1), j = idx >> SH;
            int jr = j0 + j;
            float4 v = make_float4(0.f, 0.f, 0.f, 0.f);
            if (jr < M) {
                const float* Wr = (jr < m1) ? (W1 + (size_t)jr * ldw)
                                            : (W2 + (size_t)(jr - m1) * ldw);
                int kk = k0 + (k4 << 2);
                if (kk + 3 < K) v = *reinterpret_cast<const float4*>(Wr + wofs + (k4 << 2));
                else {
                    if (kk + 0 < K) v.x = Wr[wofs + (k4 << 2) + 0];
                    if (kk + 1 < K) v.y = Wr[wofs + (k4 << 2) + 1];
                    if (kk + 2 < K) v.z = Wr[wofs + (k4 << 2) + 2];
                    if (kk + 3 < K) v.w = Wr[wofs + (k4 << 2) + 3];
                }
            }
            float* d = ws + (k4 << 2) * 132 + j;
            d[0] = v.x; d[132] = v.y; d[264] = v.z; d[396] = v.w;
        }
        bar_half(half);

        const int tj = htid & 31, tn = htid >> 5;
        float acc[4][8];
#pragma unroll
        for (int a = 0; a < 4; a++)
#pragma unroll
            for (int b = 0; b < 8; b++) acc[a][b] = 0.f;

#pragma unroll 8
        for (int k = 0; k < KC; k++) {
            float4 wv = *reinterpret_cast<const float4*>(ws + k * 132 + tj * 4);
            float4 xa = *reinterpret_cast<const float4*>(xs + k * 68 + tn * 8);
            float4 xb = *reinterpret_cast<const float4*>(xs + k * 68 + tn * 8 + 4);
            float xv[8] = {xa.x, xa.y, xa.z, xa.w, xb.x, xb.y, xb.z, xb.w};
            float wr[4] = {wv.x, wv.y, wv.z, wv.w};
#pragma unroll
            for (int jj = 0; jj < 4; jj++)
#pragma unroll
                for (int i = 0; i < 8; i++) acc[jj][i] += wr[jj] * xv[i];
        }

        if (j0 + tj * 4 < M) {
            float* base = P + (size_t)ksp * (64 * ldp) + j0 + tj * 4;
#pragma unroll
            for (int i = 0; i < 8; i++) {
                int n = tn * 8 + i;
                *reinterpret_cast<float4*>(base + (size_t)n * ldp) =
                    make_float4(acc[0][i], acc[1][i], acc[2][i], acc[3][i]);
            }
        }
        bar_half(half);
    }
}

// ---------------- attention phase A: per-warp independent score chunks ----------------
// item = (n, 64-row chunk): 1024 items, id = bid + 148*widx (spreads n over SMs).
__device__ void attnA(const float* __restrict__ encW, const float* __restrict__ wattn,
                      const float* __restrict__ battn, const float* __restrict__ bdec,
                      const int* __restrict__ len)
{
    const int widx = threadIdx.x >> 5, lane = threadIdx.x & 31;
    const int id = blockIdx.x + 148 * widx;
    if (id >= 1024) return;
    const int n = id >> 4, t0 = (id & 15) << 6;
    const int L = len[n];
    const int rows = min(64, L - t0);
    if (rows <= 0) {
        if (lane == 0) g_wchunk[id] = 0.f;
        return;
    }
    float4 awr[4], wvr[4];
#pragma unroll
    for (int q = 0; q < 4; q++) {
        int c = lane * 4 + q * 128;
        float4 s = *reinterpret_cast<const float4*>(bdec + c);
#pragma unroll
        for (int sp = 0; sp < 8; sp++)
            add4(s, *reinterpret_cast<const float4*>(g_P + OFF_W + sp * 32768 + n * 512 + c));
        awr[q] = s;
        wvr[q] = *reinterpret_cast<const float4*>(wattn + c);
    }
    const float bat = battn[0];
    const float* base = encW + ((size_t)(n << 10) + t0) * 512;
    float* weo = g_wexp + (n << 10) + t0;
    float wsum = 0.f;

    for (int rr = 0; rr < rows; rr += 8) {
        float s[8];
#pragma unroll
        for (int i = 0; i < 8; i++) {
            int r = rr + i;
            float si = 0.f;
            if (r < rows) {
                const float* rp = base + (size_t)r * 512;
#pragma unroll
                for (int q = 0; q < 4; q++) {
                    float4 v = *reinterpret_cast<const float4*>(rp + lane * 4 + q * 128);
                    si += tanh_fast(v.x + awr[q].x) * wvr[q].x
                        + tanh_fast(v.y + awr[q].y) * wvr[q].y
                        + tanh_fast(v.z + awr[q].z) * wvr[q].z
                        + tanh_fast(v.w + awr[q].w) * wvr[q].w;
                }
            }
            s[i] = si;
        }
#pragma unroll
        for (int o = 16; o > 0; o >>= 1) {
#pragma unroll
            for (int i = 0; i < 8; i++)
                s[i] += __shfl_xor_sync(0xffffffffu, s[i], o);
        }
        if (lane == 0) {
#pragma unroll
            for (int i = 0; i < 8; i++) {
                int r = rr + i;
                if (r < rows) {
                    float w = __expf(s[i] + bat);
                    weo[r] = w;
                    wsum += w;
                }
            }
        }
    }
    if (lane == 0) g_wchunk[id] = wsum;
}

// ---------------- attention phase B: per-warp independent column streams ----------------
// item = (n, colblock of 128, rowblock of 128): 2048 items, id = bid + 148*widx
__device__ void attnB(const float* __restrict__ enc, const int* __restrict__ len)
{
    const int widx = threadIdx.x >> 5, lane = threadIdx.x & 31;
    const int id = blockIdx.x + 148 * widx;
    if (id >= 2048) return;
    const int n = id >> 5, cb = (id >> 3) & 3, rb = id & 7;
    const int col = cb * 128 + lane * 4;
    const int t0 = rb << 7;
    const int L = len[n];
    const int rows = min(128, L - t0);
    float4 acc = make_float4(0.f, 0.f, 0.f, 0.f);
    if (rows > 0) {
        const float* base = enc + ((size_t)(n << 10) + t0) * 512 + col;
        const float* wp = g_wexp + (n << 10) + t0;
        int r = 0;
        for (; r + 8 <= rows; r += 8) {
            float w[8]; float4 v[8];
#pragma unroll
            for (int i = 0; i < 8; i++) {
                w[i] = wp[r + i];
                v[i] = *reinterpret_cast<const float4*>(base + (size_t)(r + i) * 512);
            }
#pragma unroll
            for (int i = 0; i < 8; i++) {
                acc.x += w[i] * v[i].x; acc.y += w[i] * v[i].y;
                acc.z += w[i] * v[i].z; acc.w += w[i] * v[i].w;
            }
        }
        for (; r < rows; r++) {
            float w = wp[r];
            float4 v = *reinterpret_cast<const float4*>(base + (size_t)r * 512);
            acc.x += w * v.x; acc.y += w * v.y; acc.z += w * v.z; acc.w += w * v.w;
        }
    }
    *reinterpret_cast<float4*>(g_part + (size_t)(n * 8 + rb) * 512 + col) = acc;
}

// ---------------- the mega kernel ----------------
struct MArgs {
    const float *enc, *encW, *dec, *sv;
    const int* len;
    const float *pw1, *pb1, *pw2, *pb2, *wdec_, *bdec;
    const float *ga_ih, *ga_bih, *ga_bhh, *wattn, *battn;
    const float *wsc, *bsc, *g1_ih, *g1_bih, *g1_bhh;
    const float *g2_ih, *g2_bih, *g2_bhh, *wout_, *bout;
    float* out;
};

__global__ __launch_bounds__(NTHR) void mega(MArgs a)
{
    extern __shared__ float sm[];
    const int tid  = threadIdx.x;
    const int half = tid >> 8;
    const int htid = tid & 255;
    float* smh = sm + half * 12800;
    const int BIGJ = 1 << 30;

    // S1: pre1 partials (M=512,K=80,KC=32,jt=4,ks=3)
    gemm_stage<32>(XDirect{a.dec, 80}, a.pw1, BIGJ, a.pw1, 80, BIGJ, 0,
                   512, 80, 4, 3, g_P + OFF_P1, 512, smh, half, htid);
    gbar(1 * NBLK);

    // S2: pre2 partials (M=256,K=512,KC=64,jt=2,ks=8); X = relu(pre1-reduce)
    gemm_stage<64>(XPre1Red{g_P + OFF_P1, a.pb1}, a.pw2, BIGJ, a.pw2, 512, BIGJ, 0,
                   256, 512, 2, 8, g_P + OFF_P2, 256, smh, half, htid);
    gbar(2 * NBLK);

    // S4: gruA input GEMM (M=1536,K=384,KC=32,jt=12,ks=12), W col jump at 256 (+512)
    gemm_stage<32>(XPre2Red{g_P + OFF_P2, a.pb2, a.sv}, a.ga_ih, BIGJ, a.ga_ih, 896,
                   256, 512, 1536, 384, 12, 12, g_P + OFF_A, 1536, smh, half, htid);
    gbar(3 * NBLK);

    // S6: wdec partials (M=512,K=512,KC=64,jt=4,ks=8); X = gruA reduce on the fly.
    {
        XGruARed xga{g_P + OFF_A, a.ga_bih, a.ga_bhh};
        for (int idx = blockIdx.x * NTHR + tid; idx < 64 * 128; idx += NBLK * NTHR) {
            int n = idx >> 7, c = (idx & 127) << 2;
            *reinterpret_cast<float4*>(g_oatt + n * 512 + c) = xga.load4(n, c);
        }
        gemm_stage<64>(xga, a.wdec_, BIGJ, a.wdec_, 512, BIGJ, 0,
                       512, 512, 4, 8, g_P + OFF_W, 512, smh, half, htid);
    }
    gbar(4 * NBLK);

    // S8a: scores — per-warp static; attW slice built from partials in-warp
    attnA(a.encW, a.wattn, a.battn, a.bdec, a.len);
    gbar(5 * NBLK);

    // S8b: weighted column sums — per-warp static
    attnB(a.enc, a.len);
    gbar(6 * NBLK);

    // S10: fused wsc|g1 GEMM (M=2048,K=1152,KC=64,jt=16,ks=18); X = out_dec on the fly.
    {
        XOdecRed xod{g_part, g_wchunk, g_oatt, a.sv};
        for (int idx = blockIdx.x * NTHR + tid; idx < 64 * 128; idx += NBLK * NTHR) {
            int n = idx >> 7, c = (idx & 127) << 2;
            *reinterpret_cast<float4*>(a.out + 10240 + (size_t)n * 512 + c) = xod.load4(n, c);
        }
        gemm_stage<64>(xod, a.wsc, 512, a.g1_ih, 1152, BIGJ, 0,
                       2048, 1152, 16, 18, g_P + OFF_G, 2048, smh, half, htid);
    }
    gbar(7 * NBLK);

    // S11: residual = sc + gru1 -> res1
    for (int idx = blockIdx.x * NTHR + tid; idx < 64 * 512; idx += NBLK * NTHR) {
        int n = idx >> 9, j = idx & 511;
        float sc = a.bsc[j], gr = a.g1_bih[j], gz = a.g1_bih[512 + j], gn = a.g1_bih[1024 + j];
        for (int s = 0; s < 18; s++) {
            const float* pp = g_P + OFF_G + (size_t)s * 131072 + (size_t)n * 2048;
            sc += pp[j]; gr += pp[512 + j]; gz += pp[1024 + j]; gn += pp[1536 + j];
        }
        g_res1[idx] = sc + gru_out(gr, gz, gn, a.g1_bhh[j], a.g1_bhh[512 + j], a.g1_bhh[1024 + j]);
    }
    gbar(8 * NBLK);

    // S12: g2 GEMM (M=1536,K=512,KC=32,jt=12,ks=16)
    gemm_stage<32>(XDirect{g_res1, 512}, a.g2_ih, BIGJ, a.g2_ih, 512, BIGJ, 0,
                   1536, 512, 12, 16, g_P + OFF_2, 1536, smh, half, htid);
    gbar(9 * NBLK);

    // S14: wout GEMM (M=160,K=512,KC=32,jt=2,ks=16); X = res1 + gru2 reduce on the fly
    gemm_stage<32>(XGru2Red{g_P + OFF_2, a.g2_bih, a.g2_bhh, g_res1},
                   a.wout_, BIGJ, a.wout_, 512, BIGJ, 0,
                   160, 512, 2, 16, g_P + OFF_O, 160, smh, half, htid);
    gbar(10 * NBLK);

    // S15: wout reduce -> d_out[0:10240]
    for (int idx = blockIdx.x * NTHR + tid; idx < 64 * 160; idx += NBLK * NTHR) {
        int n = idx / 160, j = idx - n * 160;
        float s = a.bout[j];
#pragma unroll
        for (int sp = 0; sp < 16; sp++) s += g_P[OFF_O + sp * 10240 + n * 160 + j];
        a.out[idx] = s;
    }
}

// ---------------- host orchestration ----------------
extern "C" void kernel_launch(void* const* d_in, const int* in_sizes, int n_in,
                              void* d_out, int out_size)
{
    (void)n_in; (void)out_size;
    bool dictord = (in_sizes[4] == 64);
    int b = dictord ? 5 : 4;

    MArgs a;
    a.enc   = (const float*)d_in[0];
    a.encW  = (const float*)d_in[1];
    a.dec   = (const float*)d_in[2];
    a.sv    = (const float*)d_in[3];
    a.len   = (const int*)(dictord ? d_in[4] : d_in[28]);
    a.pw1   = (const float*)d_in[b + 0];
    a.pb1   = (const float*)d_in[b + 1];
    a.pw2   = (const float*)d_in[b + 2];
    a.pb2   = (const float*)d_in[b + 3];
    a.wdec_ = (const float*)d_in[b + 4];
    a.bdec  = (const float*)d_in[b + 5];
    a.ga_ih = (const float*)d_in[b + 6];
    a.ga_bih= (const float*)d_in[b + 8];
    a.ga_bhh= (const float*)d_in[b + 9];
    a.wattn = (const float*)d_in[b + 10];
    a.battn = (const float*)d_in[b + 11];
    a.wsc   = (const float*)d_in[b + 12];
    a.bsc   = (const float*)d_in[b + 13];
    a.g1_ih = (const float*)d_in[b + 14];
    a.g1_bih= (const float*)d_in[b + 16];
    a.g1_bhh= (const float*)d_in[b + 17];
    a.g2_ih = (const float*)d_in[b + 18];
    a.g2_bih= (const float*)d_in[b + 20];
    a.g2_bhh= (const float*)d_in[b + 21];
    a.wout_ = (const float*)d_in[b + 22];
    a.bout  = (const float*)d_in[b + 23];
    a.out   = (float*)d_out;

    static bool attr_set = false;
    if (!attr_set) {
        cudaFuncSetAttribute(mega, cudaFuncAttributeMaxDynamicSharedMemorySize, 102400);
        attr_set = true;
    }

    void* sync;
    cudaGetSymbolAddress(&sync, g_sync);
    cudaMemsetAsync(sync, 0, 32 * sizeof(unsigned));

    mega<<<NBLK, NTHR, 102400>>>(a);
}

// round 13
// speedup vs baseline: 2.1481x; 1.1526x over previous
#include <cuda_runtime.h>
#include <cstdint>

// ---------------- static device scratch ----------------
__device__ __align__(16) float g_P[4276224];
__device__ __align__(16) float g_oatt[64 * 512];
__device__ __align__(16) float g_res1[64 * 512];
__device__ __align__(16) float g_part[64 * 8 * 512];
__device__ __align__(16) float g_wexp[64 * 1024];
__device__ __align__(16) float g_wchunk[512];

// partial-region offsets (floats), KC=64 everywhere
#define OFF_P1 0        // pre1:  ns=2,  ldp=512
#define OFF_P2 65536    // pre2:  ns=8,  ldp=256
#define OFF_A  196608   // gruA:  ns=6,  ldp=1536
#define OFF_W  786432   // wdec:  ns=8,  ldp=512
#define OFF_G  1048576  // wsc|g1:ns=18, ldp=2048
#define OFF_2  3407872  // g2:    ns=8,  ldp=1536
#define OFF_O  4194304  // wout:  ns=8,  ldp=160

__device__ __forceinline__ float tanh_fast(float x) {
    float y; asm("tanh.approx.f32 %0, %1;" : "=f"(y) : "f"(x)); return y;
}
__device__ __forceinline__ float gru_out(float gr, float gz, float gn,
                                         float br, float bz, float bn) {
    float r  = 1.f / (1.f + __expf(-(gr + br)));
    float z  = 1.f / (1.f + __expf(-(gz + bz)));
    float nn = tanhf(gn + r * bn);
    return (1.f - z) * nn;
}
__device__ __forceinline__ void add4(float4& a, const float4 b) {
    a.x += b.x; a.y += b.y; a.z += b.z; a.w += b.w;
}

// ---------------- X functors ----------------
struct XDirect {
    const float* X; int ldx;
    __device__ __forceinline__ float4 load4(int n, int k) const {
        return *reinterpret_cast<const float4*>(X + (size_t)n * ldx + k);
    }
    __device__ __forceinline__ float load1(int n, int k) const {
        return X[(size_t)n * ldx + k];
    }
};
struct XPre1Red {   // t1 = relu(pb1 + sum of 2 pre1 partials)
    const float* P1; const float* pb1;
    __device__ __forceinline__ float4 load4(int n, int k) const {
        float4 s = *reinterpret_cast<const float4*>(pb1 + k);
#pragma unroll
        for (int sp = 0; sp < 2; sp++)
            add4(s, *reinterpret_cast<const float4*>(P1 + sp * 32768 + n * 512 + k));
        s.x = fmaxf(s.x, 0.f); s.y = fmaxf(s.y, 0.f);
        s.z = fmaxf(s.z, 0.f); s.w = fmaxf(s.w, 0.f);
        return s;
    }
    __device__ __forceinline__ float load1(int n, int k) const {
        float s = pb1[k];
        for (int sp = 0; sp < 2; sp++) s += P1[sp * 32768 + n * 512 + k];
        return fmaxf(s, 0.f);
    }
};
struct XPre2Red {   // gruA input: [relu(pre2-reduce) (256) | sv (128)]
    const float* P2; const float* pb2; const float* sv;
    __device__ __forceinline__ float4 load4(int n, int k) const {
        if (k < 256) {
            float4 s = *reinterpret_cast<const float4*>(pb2 + k);
#pragma unroll
            for (int sp = 0; sp < 8; sp++)
                add4(s, *reinterpret_cast<const float4*>(P2 + sp * 16384 + n * 256 + k));
            s.x = fmaxf(s.x, 0.f); s.y = fmaxf(s.y, 0.f);
            s.z = fmaxf(s.z, 0.f); s.w = fmaxf(s.w, 0.f);
            return s;
        }
        return *reinterpret_cast<const float4*>(sv + n * 128 + (k - 256));
    }
    __device__ __forceinline__ float load1(int n, int k) const {
        if (k < 256) {
            float s = pb2[k];
            for (int sp = 0; sp < 8; sp++) s += P2[sp * 16384 + n * 256 + k];
            return fmaxf(s, 0.f);
        }
        return sv[n * 128 + (k - 256)];
    }
};
struct XGruARed {   // out_att element from gruA partials (6 splits, ldp=1536)
    const float* P; const float* bih; const float* bhh;
    __device__ __forceinline__ float4 load4(int n, int k) const {
        const float* b = P + (size_t)n * 1536 + k;
        float4 r = *reinterpret_cast<const float4*>(bih + k);
        float4 z = *reinterpret_cast<const float4*>(bih + 512 + k);
        float4 m = *reinterpret_cast<const float4*>(bih + 1024 + k);
#pragma unroll
        for (int sp = 0; sp < 6; sp++) {
            const float* q = b + (size_t)sp * 98304;
            add4(r, *reinterpret_cast<const float4*>(q));
            add4(z, *reinterpret_cast<const float4*>(q + 512));
            add4(m, *reinterpret_cast<const float4*>(q + 1024));
        }
        float4 br = *reinterpret_cast<const float4*>(bhh + k);
        float4 bz = *reinterpret_cast<const float4*>(bhh + 512 + k);
        float4 bn = *reinterpret_cast<const float4*>(bhh + 1024 + k);
        float4 o;
        o.x = gru_out(r.x, z.x, m.x, br.x, bz.x, bn.x);
        o.y = gru_out(r.y, z.y, m.y, br.y, bz.y, bn.y);
        o.z = gru_out(r.z, z.z, m.z, br.z, bz.z, bn.z);
        o.w = gru_out(r.w, z.w, m.w, br.w, bz.w, bn.w);
        return o;
    }
    __device__ __forceinline__ float load1(int n, int k) const {
        float gr = bih[k], gz = bih[512 + k], gn = bih[1024 + k];
        for (int sp = 0; sp < 6; sp++) {
            const float* q = P + (size_t)sp * 98304 + (size_t)n * 1536 + k;
            gr += q[0]; gz += q[512]; gn += q[1024];
        }
        return gru_out(gr, gz, gn, bhh[k], bhh[512 + k], bhh[1024 + k]);
    }
};
struct XOdecRed {   // out_dec: [attn-normalize | out_att | sv]
    const float* part; const float* wchunk; const float* oatt; const float* sv;
    __device__ __forceinline__ float4 load4(int n, int k) const {
        if (k < 512) {
            float4 s = make_float4(0.f, 0.f, 0.f, 0.f);
            float w = 0.f;
#pragma unroll
            for (int sp = 0; sp < 8; sp++) {
                add4(s, *reinterpret_cast<const float4*>(part + (size_t)(n * 8 + sp) * 512 + k));
                w += wchunk[n * 8 + sp];
            }
            float inv = 1.f / fmaxf(w, 1e-12f);
            s.x *= inv; s.y *= inv; s.z *= inv; s.w *= inv;
            return s;
        }
        if (k < 1024) return *reinterpret_cast<const float4*>(oatt + n * 512 + (k - 512));
        return *reinterpret_cast<const float4*>(sv + n * 128 + (k - 1024));
    }
    __device__ __forceinline__ float load1(int n, int k) const {
        if (k < 512) {
            float s = 0.f, w = 0.f;
            for (int sp = 0; sp < 8; sp++) {
                s += part[(size_t)(n * 8 + sp) * 512 + k];
                w += wchunk[n * 8 + sp];
            }
            return s / fmaxf(w, 1e-12f);
        }
        if (k < 1024) return oatt[n * 512 + (k - 512)];
        return sv[n * 128 + (k - 1024)];
    }
};
struct XGru2Red {   // res2 element = res1 + gru2 from partials (8 splits)
    const float* P; const float* bih; const float* bhh; const float* res1;
    __device__ __forceinline__ float4 load4(int n, int k) const {
        const float* b = P + (size_t)n * 1536 + k;
        float4 r = *reinterpret_cast<const float4*>(bih + k);
        float4 z = *reinterpret_cast<const float4*>(bih + 512 + k);
        float4 m = *reinterpret_cast<const float4*>(bih + 1024 + k);
#pragma unroll
        for (int sp = 0; sp < 8; sp++) {
            const float* q = b + (size_t)sp * 98304;
            add4(r, *reinterpret_cast<const float4*>(q));
            add4(z, *reinterpret_cast<const float4*>(q + 512));
            add4(m, *reinterpret_cast<const float4*>(q + 1024));
        }
        float4 br = *reinterpret_cast<const float4*>(bhh + k);
        float4 bz = *reinterpret_cast<const float4*>(bhh + 512 + k);
        float4 bn = *reinterpret_cast<const float4*>(bhh + 1024 + k);
        float4 rv = *reinterpret_cast<const float4*>(res1 + n * 512 + k);
        float4 o;
        o.x = gru_out(r.x, z.x, m.x, br.x, bz.x, bn.x) + rv.x;
        o.y = gru_out(r.y, z.y, m.y, br.y, bz.y, bn.y) + rv.y;
        o.z = gru_out(r.z, z.z, m.z, br.z, bz.z, bn.z) + rv.z;
        o.w = gru_out(r.w, z.w, m.w, br.w, bz.w, bn.w) + rv.w;
        return o;
    }
    __device__ __forceinline__ float load1(int n, int k) const {
        float gr = bih[k], gz = bih[512 + k], gn = bih[1024 + k];
        for (int sp = 0; sp < 8; sp++) {
            const float* q = P + (size_t)sp * 98304 + (size_t)n * 1536 + k;
            gr += q[0]; gz += q[512]; gn += q[1024];
        }
        return gru_out(gr, gz, gn, bhh[k], bhh[512 + k], bhh[1024 + k]) + res1[n * 512 + k];
    }
};

// ---------------- k-split GEMM kernel: one block = one (jt, ksp) item ----------------
struct GW {
    const float* W1; int m1; const float* W2; int ldw;
    int kjump_at, kjump_ofs, M, K, jt_n;
    float* P; int ldp; float* oatt;
};

template <class XF>
__global__ __launch_bounds__(256) void k_gemm(const XF xf, const GW g)
{
    constexpr int KC = 64, K4 = 16, SH = 4;
    extern __shared__ float smem_[];
    float* xs = smem_;             // [KC][68]
    float* ws = smem_ + KC * 68;   // [KC][132]
    const int tid = threadIdx.x;
    const int it  = blockIdx.x;
    const int ksp = it / g.jt_n;
    const int jt  = it - ksp * g.jt_n;
    const int j0  = jt << 7;
    const int k0  = ksp * KC;

    for (int idx = tid; idx < K4 * 64; idx += 256) {
        int k4 = idx & (K4 - 1), n = idx >> SH;
        int kk = k0 + (k4 << 2);
        float4 v = make_float4(0.f, 0.f, 0.f, 0.f);
        if (kk + 3 < g.K) v = xf.load4(n, kk);
        else {
            if (kk + 0 < g.K) v.x = xf.load1(n, kk + 0);
            if (kk + 1 < g.K) v.y = xf.load1(n, kk + 1);
            if (kk + 2 < g.K) v.z = xf.load1(n, kk + 2);
            if (kk + 3 < g.K) v.w = xf.load1(n, kk + 3);
        }
        float* d = xs + (k4 << 2) * 68 + n;
        d[0] = v.x; d[68] = v.y; d[136] = v.z; d[204] = v.w;
    }
    const int wofs = k0 + (k0 >= g.kjump_at ? g.kjump_ofs : 0);
    for (int idx = tid; idx < K4 * 128; idx += 256) {
        int k4 = idx & (K4 - 1), j = idx >> SH;
        int jr = j0 + j;
        float4 v = make_float4(0.f, 0.f, 0.f, 0.f);
        if (jr < g.M) {
            const float* Wr = (jr < g.m1) ? (g.W1 + (size_t)jr * g.ldw)
                                          : (g.W2 + (size_t)(jr - g.m1) * g.ldw);
            int kk = k0 + (k4 << 2);
            if (kk + 3 < g.K) v = *reinterpret_cast<const float4*>(Wr + wofs + (k4 << 2));
            else {
                if (kk + 0 < g.K) v.x = Wr[wofs + (k4 << 2) + 0];
                if (kk + 1 < g.K) v.y = Wr[wofs + (k4 << 2) + 1];
                if (kk + 2 < g.K) v.z = Wr[wofs + (k4 << 2) + 2];
                if (kk + 3 < g.K) v.w = Wr[wofs + (k4 << 2) + 3];
            }
        }
        float* d = ws + (k4 << 2) * 132 + j;
        d[0] = v.x; d[132] = v.y; d[264] = v.z; d[396] = v.w;
    }
    __syncthreads();

    // optional side-write: materialize X slice (out_att) from the gathered xs
    if (g.oatt != nullptr && jt == 0) {
        for (int idx = tid; idx < 64 * KC; idx += 256) {
            int k = idx & (KC - 1), n = idx >> 6;
            if (k0 + k < g.K) g.oatt[n * 512 + k0 + k] = xs[k * 68 + n];
        }
    }

    const int tj = tid & 31, tn = tid >> 5;
    float acc[4][8];
#pragma unroll
    for (int a = 0; a < 4; a++)
#pragma unroll
        for (int b = 0; b < 8; b++) acc[a][b] = 0.f;

#pragma unroll 8
    for (int k = 0; k < KC; k++) {
        float4 wv = *reinterpret_cast<const float4*>(ws + k * 132 + tj * 4);
        float4 xa = *reinterpret_cast<const float4*>(xs + k * 68 + tn * 8);
        float4 xb = *reinterpret_cast<const float4*>(xs + k * 68 + tn * 8 + 4);
        float xv[8] = {xa.x, xa.y, xa.z, xa.w, xb.x, xb.y, xb.z, xb.w};
        float wr[4] = {wv.x, wv.y, wv.z, wv.w};
#pragma unroll
        for (int jj = 0; jj < 4; jj++)
#pragma unroll
            for (int i = 0; i < 8; i++) acc[jj][i] += wr[jj] * xv[i];
    }

    if (j0 + tj * 4 < g.M) {
        float* base = g.P + (size_t)ksp * (64 * g.ldp) + j0 + tj * 4;
#pragma unroll
        for (int i = 0; i < 8; i++) {
            int n = tn * 8 + i;
            *reinterpret_cast<float4*>(base + (size_t)n * g.ldp) =
                make_float4(acc[0][i], acc[1][i], acc[2][i], acc[3][i]);
        }
    }
}

// ---------------- attention score kernel: block = (n, 128-row chunk) ----------------
__global__ __launch_bounds__(256) void k_score(
    const float* __restrict__ encW, const float* __restrict__ wattn,
    const float* __restrict__ battn, const float* __restrict__ bdec,
    const int* __restrict__ len)
{
    const int n = blockIdx.x >> 3, ch = blockIdx.x & 7;
    const int t0 = ch << 7;
    const int rows = min(128, len[n] - t0);
    const int tid = threadIdx.x, lane = tid & 31, w = tid >> 5;
    if (rows <= 0) {
        if (tid == 0) g_wchunk[n * 8 + ch] = 0.f;
        return;
    }
    __shared__ float aw[512], wv[512], wred[8];
    for (int c4 = tid; c4 < 128; c4 += 256) {
        int c = c4 << 2;
        float4 s = *reinterpret_cast<const float4*>(bdec + c);
#pragma unroll
        for (int sp = 0; sp < 8; sp++)
            add4(s, *reinterpret_cast<const float4*>(g_P + OFF_W + sp * 32768 + n * 512 + c));
        *reinterpret_cast<float4*>(aw + c) = s;
        *reinterpret_cast<float4*>(wv + c) = *reinterpret_cast<const float4*>(wattn + c);
    }
    __syncthreads();

    const float bat = battn[0];
    const float* base = encW + ((size_t)(n << 10) + t0) * 512;
    float* weo = g_wexp + (n << 10) + t0;
    float wsum = 0.f;
    const int r0 = w * 16;
    const int r1 = min(r0 + 16, rows);
    for (int rr = r0; rr < r1; rr += 2) {
        const bool ok1 = (rr + 1 < r1);
        const float* rp = base + (size_t)rr * 512;
        float s0 = 0.f, s1 = 0.f;
#pragma unroll
        for (int q = 0; q < 4; q++) {
            int c = lane * 4 + q * 128;
            float4 v0 = *reinterpret_cast<const float4*>(rp + c);
            float4 v1 = ok1 ? *reinterpret_cast<const float4*>(rp + 512 + c)
                            : make_float4(0.f, 0.f, 0.f, 0.f);
            float4 a = *reinterpret_cast<const float4*>(aw + c);
            float4 wq = *reinterpret_cast<const float4*>(wv + c);
            s0 += tanh_fast(v0.x + a.x) * wq.x + tanh_fast(v0.y + a.y) * wq.y
                + tanh_fast(v0.z + a.z) * wq.z + tanh_fast(v0.w + a.w) * wq.w;
            s1 += tanh_fast(v1.x + a.x) * wq.x + tanh_fast(v1.y + a.y) * wq.y
                + tanh_fast(v1.z + a.z) * wq.z + tanh_fast(v1.w + a.w) * wq.w;
        }
#pragma unroll
        for (int o = 16; o > 0; o >>= 1) {
            s0 += __shfl_xor_sync(0xffffffffu, s0, o);
            s1 += __shfl_xor_sync(0xffffffffu, s1, o);
        }
        if (lane == 0) {
            float w0 = __expf(s0 + bat);
            weo[rr] = w0; wsum += w0;
            if (ok1) { float w1 = __expf(s1 + bat); weo[rr + 1] = w1; wsum += w1; }
        }
    }
    if (lane == 0) wred[w] = wsum;
    __syncthreads();
    if (tid == 0) {
        float s = 0.f;
#pragma unroll
        for (int i = 0; i < 8; i++) s += wred[i];
        g_wchunk[n * 8 + ch] = s;
    }
}

// ---------------- weighted-sum kernel: block = (n, 128-row block), thread = 2 cols ----------------
__global__ __launch_bounds__(256) void k_attnB(const float* __restrict__ enc,
                                               const int* __restrict__ len)
{
    const int n = blockIdx.x >> 3, rb = blockIdx.x & 7;
    const int t0 = rb << 7;
    const int rows = min(128, len[n] - t0);
    const int tid = threadIdx.x;
    float2 acc = make_float2(0.f, 0.f);
    if (rows > 0) {
        const float* base = enc + ((size_t)(n << 10) + t0) * 512 + tid * 2;
        const float* wp = g_wexp + (n << 10) + t0;
        int r = 0;
        for (; r + 16 <= rows; r += 16) {
            float wv[16]; float2 vv[16];
#pragma unroll
            for (int i = 0; i < 16; i++) {
                wv[i] = wp[r + i];
                vv[i] = *reinterpret_cast<const float2*>(base + (size_t)(r + i) * 512);
            }
#pragma unroll
            for (int i = 0; i < 16; i++) {
                acc.x += wv[i] * vv[i].x;
                acc.y += wv[i] * vv[i].y;
            }
        }
        for (; r < rows; r++) {
            float wq = wp[r];
            float2 v = *reinterpret_cast<const float2*>(base + (size_t)r * 512);
            acc.x += wq * v.x; acc.y += wq * v.y;
        }
    }
    *reinterpret_cast<float2*>(g_part + (size_t)(n * 8 + rb) * 512 + tid * 2) = acc;
}

// ---------------- res1 reduce + attn output write ----------------
__global__ __launch_bounds__(256) void k_res1out(
    const float* __restrict__ bsc, const float* __restrict__ g1_bih,
    const float* __restrict__ g1_bhh, const float* __restrict__ sv,
    float* __restrict__ out)
{
    int gid = blockIdx.x * 256 + threadIdx.x;   // 0..16383 (f4 granularity)
    if (gid < 8192) {
        int n = gid >> 7, c = (gid & 127) << 2;
        float4 sc = *reinterpret_cast<const float4*>(bsc + c);
        float4 r  = *reinterpret_cast<const float4*>(g1_bih + c);
        float4 z  = *reinterpret_cast<const float4*>(g1_bih + 512 + c);
        float4 m  = *reinterpret_cast<const float4*>(g1_bih + 1024 + c);
#pragma unroll
        for (int sp = 0; sp < 18; sp++) {
            const float* pp = g_P + OFF_G + (size_t)sp * 131072 + (size_t)n * 2048;
            add4(sc, *reinterpret_cast<const float4*>(pp + c));
            add4(r,  *reinterpret_cast<const float4*>(pp + 512 + c));
            add4(z,  *reinterpret_cast<const float4*>(pp + 1024 + c));
            add4(m,  *reinterpret_cast<const float4*>(pp + 1536 + c));
        }
        float4 br = *reinterpret_cast<const float4*>(g1_bhh + c);
        float4 bz = *reinterpret_cast<const float4*>(g1_bhh + 512 + c);
        float4 bn = *reinterpret_cast<const float4*>(g1_bhh + 1024 + c);
        float4 o;
        o.x = sc.x + gru_out(r.x, z.x, m.x, br.x, bz.x, bn.x);
        o.y = sc.y + gru_out(r.y, z.y, m.y, br.y, bz.y, bn.y);
        o.z = sc.z + gru_out(r.z, z.z, m.z, br.z, bz.z, bn.z);
        o.w = sc.w + gru_out(r.w, z.w, m.w, br.w, bz.w, bn.w);
        *reinterpret_cast<float4*>(g_res1 + n * 512 + c) = o;
    } else {
        gid -= 8192;
        int n = gid >> 7, c = (gid & 127) << 2;
        XOdecRed xod{g_part, g_wchunk, g_oatt, sv};
        *reinterpret_cast<float4*>(out + 10240 + (size_t)n * 512 + c) = xod.load4(n, c);
    }
}

// ---------------- final output reduce ----------------
__global__ __launch_bounds__(256) void k_out(const float* __restrict__ bout,
                                             float* __restrict__ out)
{
    int gid = blockIdx.x * 256 + threadIdx.x;
    if (gid >= 10240) return;
    int n = gid / 160, j = gid - n * 160;
    float s = bout[j];
#pragma unroll
    for (int sp = 0; sp < 8; sp++) s += g_P[OFF_O + sp * 10240 + n * 160 + j];
    out[gid] = s;
}

// ---------------- host orchestration ----------------
#define GSMEM 51200

extern "C" void kernel_launch(void* const* d_in, const int* in_sizes, int n_in,
                              void* d_out, int out_size)
{
    (void)n_in; (void)out_size;
    bool dictord = (in_sizes[4] == 64);
    int b = dictord ? 5 : 4;

    const float* enc   = (const float*)d_in[0];
    const float* encW  = (const float*)d_in[1];
    const float* dec   = (const float*)d_in[2];
    const float* sv    = (const float*)d_in[3];
    const int*   len   = (const int*)(dictord ? d_in[4] : d_in[28]);
    const float* pw1   = (const float*)d_in[b + 0];
    const float* pb1   = (const float*)d_in[b + 1];
    const float* pw2   = (const float*)d_in[b + 2];
    const float* pb2   = (const float*)d_in[b + 3];
    const float* wdec_ = (const float*)d_in[b + 4];
    const float* bdec  = (const float*)d_in[b + 5];
    const float* ga_ih = (const float*)d_in[b + 6];
    const float* ga_bih= (const float*)d_in[b + 8];
    const float* ga_bhh= (const float*)d_in[b + 9];
    const float* wattn = (const float*)d_in[b + 10];
    const float* battn = (const float*)d_in[b + 11];
    const float* wsc   = (const float*)d_in[b + 12];
    const float* bsc   = (const float*)d_in[b + 13];
    const float* g1_ih = (const float*)d_in[b + 14];
    const float* g1_bih= (const float*)d_in[b + 16];
    const float* g1_bhh= (const float*)d_in[b + 17];
    const float* g2_ih = (const float*)d_in[b + 18];
    const float* g2_bih= (const float*)d_in[b + 20];
    const float* g2_bhh= (const float*)d_in[b + 21];
    const float* wout_ = (const float*)d_in[b + 22];
    const float* bout  = (const float*)d_in[b + 23];
    float* out = (float*)d_out;

    float *P, *oatt, *res1, *part, *wchunk;
    cudaGetSymbolAddress((void**)&P,      g_P);
    cudaGetSymbolAddress((void**)&oatt,   g_oatt);
    cudaGetSymbolAddress((void**)&res1,   g_res1);
    cudaGetSymbolAddress((void**)&part,   g_part);
    cudaGetSymbolAddress((void**)&wchunk, g_wchunk);

    static bool attr_set = false;
    if (!attr_set) {
        cudaFuncSetAttribute(k_gemm<XDirect>,  cudaFuncAttributeMaxDynamicSharedMemorySize, GSMEM);
        cudaFuncSetAttribute(k_gemm<XPre1Red>, cudaFuncAttributeMaxDynamicSharedMemorySize, GSMEM);
        cudaFuncSetAttribute(k_gemm<XPre2Red>, cudaFuncAttributeMaxDynamicSharedMemorySize, GSMEM);
        cudaFuncSetAttribute(k_gemm<XGruARed>, cudaFuncAttributeMaxDynamicSharedMemorySize, GSMEM);
        cudaFuncSetAttribute(k_gemm<XOdecRed>, cudaFuncAttributeMaxDynamicSharedMemorySize, GSMEM);
        cudaFuncSetAttribute(k_gemm<XGru2Red>, cudaFuncAttributeMaxDynamicSharedMemorySize, GSMEM);
        attr_set = true;
    }

    const int BIGJ = 1 << 30;

    // 1. pre1 partials (M=512, K=80, jt=4, ks=2) -> 8 blocks
    k_gemm<XDirect><<<8, 256, GSMEM>>>(XDirect{dec, 80},
        GW{pw1, BIGJ, pw1, 80, BIGJ, 0, 512, 80, 4, P + OFF_P1, 512, nullptr});
    // 2. pre2 partials (M=256, K=512, jt=2, ks=8) -> 16 blocks
    k_gemm<XPre1Red><<<16, 256, GSMEM>>>(XPre1Red{P + OFF_P1, pb1},
        GW{pw2, BIGJ, pw2, 512, BIGJ, 0, 256, 512, 2, P + OFF_P2, 256, nullptr});
    // 3. gruA partials (M=1536, K=384, jt=12, ks=6), W col jump at 256 (+512) -> 72 blocks
    k_gemm<XPre2Red><<<72, 256, GSMEM>>>(XPre2Red{P + OFF_P2, pb2, sv},
        GW{ga_ih, BIGJ, ga_ih, 896, 256, 512, 1536, 384, 12, P + OFF_A, 1536, nullptr});
    // 4. wdec partials (M=512, K=512, jt=4, ks=8) + side-write out_att -> 32 blocks
    k_gemm<XGruARed><<<32, 256, GSMEM>>>(XGruARed{P + OFF_A, ga_bih, ga_bhh},
        GW{wdec_, BIGJ, wdec_, 512, BIGJ, 0, 512, 512, 4, P + OFF_W, 512, oatt});
    // 5. scores (512 blocks)
    k_score<<<512, 256>>>(encW, wattn, battn, bdec, len);
    // 6. weighted column sums (512 blocks)
    k_attnB<<<512, 256>>>(enc, len);
    // 7. fused wsc|g1 partials (M=2048, K=1152, jt=16, ks=18) -> 288 blocks
    k_gemm<XOdecRed><<<288, 256, GSMEM>>>(XOdecRed{part, wchunk, oatt, sv},
        GW{wsc, 512, g1_ih, 1152, BIGJ, 0, 2048, 1152, 16, P + OFF_G, 2048, nullptr});
    // 8. res1 reduce + attn-out write (64 blocks)
    k_res1out<<<64, 256>>>(bsc, g1_bih, g1_bhh, sv, out);
    // 9. g2 partials (M=1536, K=512, jt=12, ks=8) -> 96 blocks
    k_gemm<XDirect><<<96, 256, GSMEM>>>(XDirect{res1, 512},
        GW{g2_ih, BIGJ, g2_ih, 512, BIGJ, 0, 1536, 512, 12, P + OFF_2, 1536, nullptr});
    // 10. wout partials (M=160, K=512, jt=2, ks=8); X = res1 + gru2 on the fly -> 16 blocks
    k_gemm<XGru2Red><<<16, 256, GSMEM>>>(XGru2Red{P + OFF_2, g2_bih, g2_bhh, res1},
        GW{wout_, BIGJ, wout_, 512, BIGJ, 0, 160, 512, 2, P + OFF_O, 160, nullptr});
    // 11. output reduce (40 blocks)
    k_out<<<40, 256>>>(bout, out);
}

// round 14
// speedup vs baseline: 2.6093x; 1.2147x over previous
#include <cuda_runtime.h>
#include <cstdint>

// ---------------- static device scratch ----------------
__device__ __align__(16) float g_P[6160384];
__device__ __align__(16) float g_xga[64 * 384];
__device__ __align__(16) float g_oatt[64 * 512];
__device__ __align__(16) float g_attW[64 * 512];
__device__ __align__(16) float g_odec[64 * 1152];
__device__ __align__(16) float g_res1[64 * 512];
__device__ __align__(16) float g_part[64 * 8 * 512];
__device__ __align__(16) float g_wexp[64 * 1024];
__device__ __align__(16) float g_wchunk[512];

// partial-region offsets (floats)
#define OFF_P1 0        // pre1:  ns=3,  ldp=512
#define OFF_P2 98304    // pre2:  ns=16, ldp=256
#define OFF_A  360448   // gruA:  ns=12, ldp=1536
#define OFF_W  1540096  // wdec:  ns=16, ldp=512
#define OFF_G  2064384  // wsc|g1:ns=18, ldp=2048
#define OFF_2  4423680  // g2:    ns=16, ldp=1536
#define OFF_O  5996544  // wout:  ns=16, ldp=160

__device__ __forceinline__ float tanh_fast(float x) {
    float y; asm("tanh.approx.f32 %0, %1;" : "=f"(y) : "f"(x)); return y;
}
__device__ __forceinline__ float gru_out(float gr, float gz, float gn,
                                         float br, float bz, float bn) {
    float r  = 1.f / (1.f + __expf(-(gr + br)));
    float z  = 1.f / (1.f + __expf(-(gz + bz)));
    float nn = tanhf(gn + r * bn);
    return (1.f - z) * nn;
}
__device__ __forceinline__ void add4(float4& a, const float4 b) {
    a.x += b.x; a.y += b.y; a.z += b.z; a.w += b.w;
}

// ---------------- X functors ----------------
struct XDirect {
    const float* X; int ldx;
    __device__ __forceinline__ float4 load4(int n, int k) const {
        return *reinterpret_cast<const float4*>(X + (size_t)n * ldx + k);
    }
    __device__ __forceinline__ float load1(int n, int k) const {
        return X[(size_t)n * ldx + k];
    }
};
struct XPre1Red {   // t1 = relu(pb1 + sum of 3 pre1 partials)
    const float* P1; const float* pb1;
    __device__ __forceinline__ float4 load4(int n, int k) const {
        float4 s = *reinterpret_cast<const float4*>(pb1 + k);
#pragma unroll
        for (int sp = 0; sp < 3; sp++)
            add4(s, *reinterpret_cast<const float4*>(P1 + sp * 32768 + n * 512 + k));
        s.x = fmaxf(s.x, 0.f); s.y = fmaxf(s.y, 0.f);
        s.z = fmaxf(s.z, 0.f); s.w = fmaxf(s.w, 0.f);
        return s;
    }
    __device__ __forceinline__ float load1(int n, int k) const {
        float s = pb1[k];
        for (int sp = 0; sp < 3; sp++) s += P1[sp * 32768 + n * 512 + k];
        return fmaxf(s, 0.f);
    }
};
struct XGru2Red {   // res2 = res1 + gru2 from 16 partials (ldp=1536)
    const float* P; const float* bih; const float* bhh; const float* res1;
    __device__ __forceinline__ float4 load4(int n, int k) const {
        const float* b = P + (size_t)n * 1536 + k;
        float4 r = *reinterpret_cast<const float4*>(bih + k);
        float4 z = *reinterpret_cast<const float4*>(bih + 512 + k);
        float4 m = *reinterpret_cast<const float4*>(bih + 1024 + k);
#pragma unroll
        for (int sp = 0; sp < 16; sp++) {
            const float* q = b + (size_t)sp * 98304;
            add4(r, *reinterpret_cast<const float4*>(q));
            add4(z, *reinterpret_cast<const float4*>(q + 512));
            add4(m, *reinterpret_cast<const float4*>(q + 1024));
        }
        float4 br = *reinterpret_cast<const float4*>(bhh + k);
        float4 bz = *reinterpret_cast<const float4*>(bhh + 512 + k);
        float4 bn = *reinterpret_cast<const float4*>(bhh + 1024 + k);
        float4 rv = *reinterpret_cast<const float4*>(res1 + n * 512 + k);
        float4 o;
        o.x = gru_out(r.x, z.x, m.x, br.x, bz.x, bn.x) + rv.x;
        o.y = gru_out(r.y, z.y, m.y, br.y, bz.y, bn.y) + rv.y;
        o.z = gru_out(r.z, z.z, m.z, br.z, bz.z, bn.z) + rv.z;
        o.w = gru_out(r.w, z.w, m.w, br.w, bz.w, bn.w) + rv.w;
        return o;
    }
    __device__ __forceinline__ float load1(int n, int k) const {
        float gr = bih[k], gz = bih[512 + k], gn = bih[1024 + k];
        for (int sp = 0; sp < 16; sp++) {
            const float* q = P + (size_t)sp * 98304 + (size_t)n * 1536 + k;
            gr += q[0]; gz += q[512]; gn += q[1024];
        }
        return gru_out(gr, gz, gn, bhh[k], bhh[512 + k], bhh[1024 + k]) + res1[n * 512 + k];
    }
};

// ---------------- k-split GEMM: 512 threads, tile 128j x 64n, thread 4j x 4n ----------------
struct GW {
    const float* W1; int m1; const float* W2; int ldw;
    int kjump_at, kjump_ofs, M, K, jt_n;
    float* P; int ldp;
};

template <int KC, class XF>
__global__ __launch_bounds__(512) void k_gemm(const XF xf, const GW g)
{
    constexpr int K4 = KC / 4;
    extern __shared__ float smem_[];
    float* xs = smem_;             // [KC][68]
    float* ws = smem_ + KC * 68;   // [KC][132]
    const int tid = threadIdx.x;
    const int it  = blockIdx.x;
    const int ksp = it / g.jt_n;
    const int jt  = it - ksp * g.jt_n;
    const int j0  = jt << 7;
    const int k0  = ksp * KC;

    for (int idx = tid; idx < K4 * 64; idx += 512) {
        int k4 = idx & (K4 - 1), n = idx / K4;
        int kk = k0 + (k4 << 2);
        float4 v = make_float4(0.f, 0.f, 0.f, 0.f);
        if (kk + 3 < g.K) v = xf.load4(n, kk);
        else {
            if (kk + 0 < g.K) v.x = xf.load1(n, kk + 0);
            if (kk + 1 < g.K) v.y = xf.load1(n, kk + 1);
            if (kk + 2 < g.K) v.z = xf.load1(n, kk + 2);
            if (kk + 3 < g.K) v.w = xf.load1(n, kk + 3);
        }
        float* d = xs + (k4 << 2) * 68 + n;
        d[0] = v.x; d[68] = v.y; d[136] = v.z; d[204] = v.w;
    }
    const int wofs = k0 + (k0 >= g.kjump_at ? g.kjump_ofs : 0);
    for (int idx = tid; idx < K4 * 128; idx += 512) {
        int k4 = idx & (K4 - 1), j = idx / K4;
        int jr = j0 + j;
        float4 v = make_float4(0.f, 0.f, 0.f, 0.f);
        if (jr < g.M) {
            const float* Wr = (jr < g.m1) ? (g.W1 + (size_t)jr * g.ldw)
                                          : (g.W2 + (size_t)(jr - g.m1) * g.ldw);
            int kk = k0 + (k4 << 2);
            if (kk + 3 < g.K) v = *reinterpret_cast<const float4*>(Wr + wofs + (k4 << 2));
            else {
                if (kk + 0 < g.K) v.x = Wr[wofs + (k4 << 2) + 0];
                if (kk + 1 < g.K) v.y = Wr[wofs + (k4 << 2) + 1];
                if (kk + 2 < g.K) v.z = Wr[wofs + (k4 << 2) + 2];
                if (kk + 3 < g.K) v.w = Wr[wofs + (k4 << 2) + 3];
            }
        }
        float* d = ws + (k4 << 2) * 132 + j;
        d[0] = v.x; d[132] = v.y; d[264] = v.z; d[396] = v.w;
    }
    __syncthreads();

    const int tj = tid & 31, tn = tid >> 5;
    float acc[4][4];
#pragma unroll
    for (int a = 0; a < 4; a++)
#pragma unroll
        for (int b = 0; b < 4; b++) acc[a][b] = 0.f;

#pragma unroll 8
    for (int k = 0; k < KC; k++) {
        float4 wv = *reinterpret_cast<const float4*>(ws + k * 132 + tj * 4);
        float4 xv = *reinterpret_cast<const float4*>(xs + k * 68 + tn * 4);
        float xr[4] = {xv.x, xv.y, xv.z, xv.w};
        float wr[4] = {wv.x, wv.y, wv.z, wv.w};
#pragma unroll
        for (int jj = 0; jj < 4; jj++)
#pragma unroll
            for (int i = 0; i < 4; i++) acc[jj][i] += wr[jj] * xr[i];
    }

    if (j0 + tj * 4 < g.M) {
        float* base = g.P + (size_t)ksp * (64 * g.ldp) + j0 + tj * 4;
#pragma unroll
        for (int i = 0; i < 4; i++) {
            int n = tn * 4 + i;
            *reinterpret_cast<float4*>(base + (size_t)n * g.ldp) =
                make_float4(acc[0][i], acc[1][i], acc[2][i], acc[3][i]);
        }
    }
}

// ---------------- tiny reduce kernels (full occupancy, f4-granular) ----------------
// xga = [relu(pb2 + sum16 P2) | sv]
__global__ __launch_bounds__(256) void k_xga(const float* __restrict__ pb2,
                                             const float* __restrict__ sv)
{
    int gid = blockIdx.x * 256 + threadIdx.x;      // 64*96 f4
    if (gid >= 6144) return;
    int n = gid / 96, c4 = gid - n * 96;
    int c = c4 << 2;
    float4 v;
    if (c < 256) {
        v = *reinterpret_cast<const float4*>(pb2 + c);
#pragma unroll
        for (int sp = 0; sp < 16; sp++)
            add4(v, *reinterpret_cast<const float4*>(g_P + OFF_P2 + sp * 16384 + n * 256 + c));
        v.x = fmaxf(v.x, 0.f); v.y = fmaxf(v.y, 0.f);
        v.z = fmaxf(v.z, 0.f); v.w = fmaxf(v.w, 0.f);
    } else {
        v = *reinterpret_cast<const float4*>(sv + n * 128 + (c - 256));
    }
    *reinterpret_cast<float4*>(g_xga + n * 384 + c) = v;
}

// oatt = gruA(sum12 PA)
__global__ __launch_bounds__(256) void k_oatt(const float* __restrict__ bih,
                                              const float* __restrict__ bhh)
{
    int gid = blockIdx.x * 256 + threadIdx.x;      // 64*128 f4
    if (gid >= 8192) return;
    int n = gid >> 7, c = (gid & 127) << 2;
    float4 r = *reinterpret_cast<const float4*>(bih + c);
    float4 z = *reinterpret_cast<const float4*>(bih + 512 + c);
    float4 m = *reinterpret_cast<const float4*>(bih + 1024 + c);
#pragma unroll
    for (int sp = 0; sp < 12; sp++) {
        const float* q = g_P + OFF_A + (size_t)sp * 98304 + (size_t)n * 1536 + c;
        add4(r, *reinterpret_cast<const float4*>(q));
        add4(z, *reinterpret_cast<const float4*>(q + 512));
        add4(m, *reinterpret_cast<const float4*>(q + 1024));
    }
    float4 br = *reinterpret_cast<const float4*>(bhh + c);
    float4 bz = *reinterpret_cast<const float4*>(bhh + 512 + c);
    float4 bn = *reinterpret_cast<const float4*>(bhh + 1024 + c);
    float4 o;
    o.x = gru_out(r.x, z.x, m.x, br.x, bz.x, bn.x);
    o.y = gru_out(r.y, z.y, m.y, br.y, bz.y, bn.y);
    o.z = gru_out(r.z, z.z, m.z, br.z, bz.z, bn.z);
    o.w = gru_out(r.w, z.w, m.w, br.w, bz.w, bn.w);
    *reinterpret_cast<float4*>(g_oatt + n * 512 + c) = o;
}

// attW = bdec + sum16 PW
__global__ __launch_bounds__(256) void k_attw(const float* __restrict__ bdec)
{
    int gid = blockIdx.x * 256 + threadIdx.x;      // 64*128 f4
    if (gid >= 8192) return;
    int n = gid >> 7, c = (gid & 127) << 2;
    float4 s = *reinterpret_cast<const float4*>(bdec + c);
#pragma unroll
    for (int sp = 0; sp < 16; sp++)
        add4(s, *reinterpret_cast<const float4*>(g_P + OFF_W + sp * 32768 + n * 512 + c));
    *reinterpret_cast<float4*>(g_attW + n * 512 + c) = s;
}

// odec = [attn_norm | oatt | sv]; also writes attn_applied to d_out
__global__ __launch_bounds__(256) void k_odec(const float* __restrict__ sv,
                                              float* __restrict__ out)
{
    int gid = blockIdx.x * 256 + threadIdx.x;      // 64*288 f4
    if (gid >= 18432) return;
    int n = gid / 288, c4 = gid - n * 288;
    int c = c4 << 2;
    float4 v;
    if (c < 512) {
        v = make_float4(0.f, 0.f, 0.f, 0.f);
        float w = 0.f;
#pragma unroll
        for (int sp = 0; sp < 8; sp++) {
            add4(v, *reinterpret_cast<const float4*>(g_part + (size_t)(n * 8 + sp) * 512 + c));
            w += g_wchunk[n * 8 + sp];
        }
        float inv = 1.f / fmaxf(w, 1e-12f);
        v.x *= inv; v.y *= inv; v.z *= inv; v.w *= inv;
        *reinterpret_cast<float4*>(out + 10240 + (size_t)n * 512 + c) = v;
    } else if (c < 1024) {
        v = *reinterpret_cast<const float4*>(g_oatt + n * 512 + (c - 512));
    } else {
        v = *reinterpret_cast<const float4*>(sv + n * 128 + (c - 1024));
    }
    *reinterpret_cast<float4*>(g_odec + n * 1152 + c) = v;
}

// res1 = bsc + sum18(sc) + gru1(sum18)
__global__ __launch_bounds__(256) void k_res1(const float* __restrict__ bsc,
                                              const float* __restrict__ bih,
                                              const float* __restrict__ bhh)
{
    int gid = blockIdx.x * 256 + threadIdx.x;      // 64*128 f4
    if (gid >= 8192) return;
    int n = gid >> 7, c = (gid & 127) << 2;
    float4 sc = *reinterpret_cast<const float4*>(bsc + c);
    float4 r  = *reinterpret_cast<const float4*>(bih + c);
    float4 z  = *reinterpret_cast<const float4*>(bih + 512 + c);
    float4 m  = *reinterpret_cast<const float4*>(bih + 1024 + c);
#pragma unroll
    for (int sp = 0; sp < 18; sp++) {
        const float* pp = g_P + OFF_G + (size_t)sp * 131072 + (size_t)n * 2048;
        add4(sc, *reinterpret_cast<const float4*>(pp + c));
        add4(r,  *reinterpret_cast<const float4*>(pp + 512 + c));
        add4(z,  *reinterpret_cast<const float4*>(pp + 1024 + c));
        add4(m,  *reinterpret_cast<const float4*>(pp + 1536 + c));
    }
    float4 br = *reinterpret_cast<const float4*>(bhh + c);
    float4 bz = *reinterpret_cast<const float4*>(bhh + 512 + c);
    float4 bn = *reinterpret_cast<const float4*>(bhh + 1024 + c);
    float4 o;
    o.x = sc.x + gru_out(r.x, z.x, m.x, br.x, bz.x, bn.x);
    o.y = sc.y + gru_out(r.y, z.y, m.y, br.y, bz.y, bn.y);
    o.z = sc.z + gru_out(r.z, z.z, m.z, br.z, bz.z, bn.z);
    o.w = sc.w + gru_out(r.w, z.w, m.w, br.w, bz.w, bn.w);
    *reinterpret_cast<float4*>(g_res1 + n * 512 + c) = o;
}

// ---------------- attention score kernel: block = (n, 128-row chunk) ----------------
__global__ __launch_bounds__(256) void k_score(
    const float* __restrict__ encW, const float* __restrict__ wattn,
    const float* __restrict__ battn, const int* __restrict__ len)
{
    const int n = blockIdx.x >> 3, ch = blockIdx.x & 7;
    const int t0 = ch << 7;
    const int rows = min(128, len[n] - t0);
    const int tid = threadIdx.x, lane = tid & 31, w = tid >> 5;
    if (rows <= 0) {
        if (tid == 0) g_wchunk[n * 8 + ch] = 0.f;
        return;
    }
    __shared__ float aw[512], wv[512], wred[8];
    for (int c4 = tid; c4 < 128; c4 += 256) {
        int c = c4 << 2;
        *reinterpret_cast<float4*>(aw + c) = *reinterpret_cast<const float4*>(g_attW + n * 512 + c);
        *reinterpret_cast<float4*>(wv + c) = *reinterpret_cast<const float4*>(wattn + c);
    }
    __syncthreads();

    const float bat = battn[0];
    const float* base = encW + ((size_t)(n << 10) + t0) * 512;
    float* weo = g_wexp + (n << 10) + t0;
    float wsum = 0.f;
    const int r0 = w * 16;
    const int r1 = min(r0 + 16, rows);
    for (int rr = r0; rr < r1; rr += 2) {
        const bool ok1 = (rr + 1 < r1);
        const float* rp = base + (size_t)rr * 512;
        float s0 = 0.f, s1 = 0.f;
#pragma unroll
        for (int q = 0; q < 4; q++) {
            int c = lane * 4 + q * 128;
            float4 v0 = *reinterpret_cast<const float4*>(rp + c);
            float4 v1 = ok1 ? *reinterpret_cast<const float4*>(rp + 512 + c)
                            : make_float4(0.f, 0.f, 0.f, 0.f);
            float4 a = *reinterpret_cast<const float4*>(aw + c);
            float4 wq = *reinterpret_cast<const float4*>(wv + c);
            s0 += tanh_fast(v0.x + a.x) * wq.x + tanh_fast(v0.y + a.y) * wq.y
                + tanh_fast(v0.z + a.z) * wq.z + tanh_fast(v0.w + a.w) * wq.w;
            s1 += tanh_fast(v1.x + a.x) * wq.x + tanh_fast(v1.y + a.y) * wq.y
                + tanh_fast(v1.z + a.z) * wq.z + tanh_fast(v1.w + a.w) * wq.w;
        }
#pragma unroll
        for (int o = 16; o > 0; o >>= 1) {
            s0 += __shfl_xor_sync(0xffffffffu, s0, o);
            s1 += __shfl_xor_sync(0xffffffffu, s1, o);
        }
        if (lane == 0) {
            float w0 = __expf(s0 + bat);
            weo[rr] = w0; wsum += w0;
            if (ok1) { float w1 = __expf(s1 + bat); weo[rr + 1] = w1; wsum += w1; }
        }
    }
    if (lane == 0) wred[w] = wsum;
    __syncthreads();
    if (tid == 0) {
        float s = 0.f;
#pragma unroll
        for (int i = 0; i < 8; i++) s += wred[i];
        g_wchunk[n * 8 + ch] = s;
    }
}

// ---------------- weighted-sum kernel: block = (n, 128-row block), thread = 2 cols ----------------
__global__ __launch_bounds__(256) void k_attnB(const float* __restrict__ enc,
                                               const int* __restrict__ len)
{
    const int n = blockIdx.x >> 3, rb = blockIdx.x & 7;
    const int t0 = rb << 7;
    const int rows = min(128, len[n] - t0);
    const int tid = threadIdx.x;
    float2 acc = make_float2(0.f, 0.f);
    if (rows > 0) {
        const float* base = enc + ((size_t)(n << 10) + t0) * 512 + tid * 2;
        const float* wp = g_wexp + (n << 10) + t0;
        int r = 0;
        for (; r + 16 <= rows; r += 16) {
            float wv[16]; float2 vv[16];
#pragma unroll
            for (int i = 0; i < 16; i++) {
                wv[i] = wp[r + i];
                vv[i] = *reinterpret_cast<const float2*>(base + (size_t)(r + i) * 512);
            }
#pragma unroll
            for (int i = 0; i < 16; i++) {
                acc.x += wv[i] * vv[i].x;
                acc.y += wv[i] * vv[i].y;
            }
        }
        for (; r < rows; r++) {
            float wq = wp[r];
            float2 v = *reinterpret_cast<const float2*>(base + (size_t)r * 512);
            acc.x += wq * v.x; acc.y += wq * v.y;
        }
    }
    *reinterpret_cast<float2*>(g_part + (size_t)(n * 8 + rb) * 512 + tid * 2) = acc;
}

// ---------------- final output reduce ----------------
__global__ __launch_bounds__(256) void k_out(const float* __restrict__ bout,
                                             float* __restrict__ out)
{
    int gid = blockIdx.x * 256 + threadIdx.x;
    if (gid >= 10240) return;
    int n = gid / 160, j = gid - n * 160;
    float s = bout[j];
#pragma unroll
    for (int sp = 0; sp < 16; sp++) s += g_P[OFF_O + sp * 10240 + n * 160 + j];
    out[gid] = s;
}

// ---------------- host orchestration ----------------
extern "C" void kernel_launch(void* const* d_in, const int* in_sizes, int n_in,
                              void* d_out, int out_size)
{
    (void)n_in; (void)out_size;
    bool dictord = (in_sizes[4] == 64);
    int b = dictord ? 5 : 4;

    const float* enc   = (const float*)d_in[0];
    const float* encW  = (const float*)d_in[1];
    const float* dec   = (const float*)d_in[2];
    const float* sv    = (const float*)d_in[3];
    const int*   len   = (const int*)(dictord ? d_in[4] : d_in[28]);
    const float* pw1   = (const float*)d_in[b + 0];
    const float* pb1   = (const float*)d_in[b + 1];
    const float* pw2   = (const float*)d_in[b + 2];
    const float* pb2   = (const float*)d_in[b + 3];
    const float* wdec_ = (const float*)d_in[b + 4];
    const float* bdec  = (const float*)d_in[b + 5];
    const float* ga_ih = (const float*)d_in[b + 6];
    const float* ga_bih= (const float*)d_in[b + 8];
    const float* ga_bhh= (const float*)d_in[b + 9];
    const float* wattn = (const float*)d_in[b + 10];
    const float* battn = (const float*)d_in[b + 11];
    const float* wsc   = (const float*)d_in[b + 12];
    const float* bsc   = (const float*)d_in[b + 13];
    const float* g1_ih = (const float*)d_in[b + 14];
    const float* g1_bih= (const float*)d_in[b + 16];
    const float* g1_bhh= (const float*)d_in[b + 17];
    const float* g2_ih = (const float*)d_in[b + 18];
    const float* g2_bih= (const float*)d_in[b + 20];
    const float* g2_bhh= (const float*)d_in[b + 21];
    const float* wout_ = (const float*)d_in[b + 22];
    const float* bout  = (const float*)d_in[b + 23];
    float* out = (float*)d_out;

    float *P, *xga, *oatt, *odec, *res1;
    cudaGetSymbolAddress((void**)&P,    g_P);
    cudaGetSymbolAddress((void**)&xga,  g_xga);
    cudaGetSymbolAddress((void**)&oatt, g_oatt);
    cudaGetSymbolAddress((void**)&odec, g_odec);
    cudaGetSymbolAddress((void**)&res1, g_res1);

    static bool attr_set = false;
    if (!attr_set) {
        cudaFuncSetAttribute(k_gemm<32, XDirect>,  cudaFuncAttributeMaxDynamicSharedMemorySize, 25600);
        cudaFuncSetAttribute(k_gemm<32, XPre1Red>, cudaFuncAttributeMaxDynamicSharedMemorySize, 25600);
        cudaFuncSetAttribute(k_gemm<32, XGru2Red>, cudaFuncAttributeMaxDynamicSharedMemorySize, 25600);
        cudaFuncSetAttribute(k_gemm<64, XDirect>,  cudaFuncAttributeMaxDynamicSharedMemorySize, 51200);
        attr_set = true;
    }

    const int BIGJ = 1 << 30;

    // 1. pre1 partials (M=512, K=80, jt=4, ks=3) -> 12 blocks
    k_gemm<32, XDirect><<<12, 512, 25600>>>(XDirect{dec, 80},
        GW{pw1, BIGJ, pw1, 80, BIGJ, 0, 512, 80, 4, P + OFF_P1, 512});
    // 2. pre2 partials (M=256, K=512, jt=2, ks=16) -> 32 blocks
    k_gemm<32, XPre1Red><<<32, 512, 25600>>>(XPre1Red{P + OFF_P1, pb1},
        GW{pw2, BIGJ, pw2, 512, BIGJ, 0, 256, 512, 2, P + OFF_P2, 256});
    // 3. xga = [relu(pre2) | sv]
    k_xga<<<24, 256>>>(pb2, sv);
    // 4. gruA partials (M=1536, K=384, jt=12, ks=12), W col jump at 256 (+512) -> 144 blocks
    k_gemm<32, XDirect><<<144, 512, 25600>>>(XDirect{xga, 384},
        GW{ga_ih, BIGJ, ga_ih, 896, 256, 512, 1536, 384, 12, P + OFF_A, 1536});
    // 5. oatt = gruA reduce
    k_oatt<<<32, 256>>>(ga_bih, ga_bhh);
    // 6. wdec partials (M=512, K=512, jt=4, ks=16) -> 64 blocks
    k_gemm<32, XDirect><<<64, 512, 25600>>>(XDirect{oatt, 512},
        GW{wdec_, BIGJ, wdec_, 512, BIGJ, 0, 512, 512, 4, P + OFF_W, 512});
    // 7. attW materialize
    k_attw<<<32, 256>>>(bdec);
    // 8. scores (512 blocks)
    k_score<<<512, 256>>>(encW, wattn, battn, len);
    // 9. weighted column sums (512 blocks)
    k_attnB<<<512, 256>>>(enc, len);
    // 10. odec materialize + attn output write
    k_odec<<<72, 256>>>(sv, out);
    // 11. fused wsc|g1 partials (M=2048, K=1152, KC=64, jt=16, ks=18) -> 288 blocks
    k_gemm<64, XDirect><<<288, 512, 51200>>>(XDirect{odec, 1152},
        GW{wsc, 512, g1_ih, 1152, BIGJ, 0, 2048, 1152, 16, P + OFF_G, 2048});
    // 12. res1 reduce
    k_res1<<<32, 256>>>(bsc, g1_bih, g1_bhh);
    // 13. g2 partials (M=1536, K=512, jt=12, ks=16) -> 192 blocks
    k_gemm<32, XDirect><<<192, 512, 25600>>>(XDirect{res1, 512},
        GW{g2_ih, BIGJ, g2_ih, 512, BIGJ, 0, 1536, 512, 12, P + OFF_2, 1536});
    // 14. wout partials (M=160, K=512, jt=2, ks=16); X = res1 + gru2 on the fly -> 32 blocks
    k_gemm<32, XGru2Red><<<32, 512, 25600>>>(XGru2Red{P + OFF_2, g2_bih, g2_bhh, res1},
        GW{wout_, BIGJ, wout_, 512, BIGJ, 0, 160, 512, 2, P + OFF_O, 160});
    // 15. output reduce (40 blocks)
    k_out<<<40, 256>>>(bout, out);
}

// round 15
// speedup vs baseline: 2.7237x; 1.0438x over previous
#include <cuda_runtime.h>
#include <cstdint>

// ---------------- static device scratch ----------------
__device__ __align__(16) float g_P[6160384];
__device__ __align__(16) float g_xga[64 * 384];
__device__ __align__(16) float g_oatt[64 * 512];
__device__ __align__(16) float g_attW[64 * 512];
__device__ __align__(16) float g_odec[64 * 1152];
__device__ __align__(16) float g_res1[64 * 512];
__device__ __align__(16) float g_part[64 * 8 * 512];
__device__ __align__(16) float g_wchunk[512];

// partial-region offsets (floats)
#define OFF_P1 0        // pre1:  ns=2,  ldp=512   (KC=64)
#define OFF_P2 65536    // pre2:  ns=8,  ldp=256   (KC=64)
#define OFF_A  196608   // gruA:  ns=12, ldp=1536  (KC=32)
#define OFF_W  1376256  // wdec:  ns=16, ldp=512   (KC=32)
#define OFF_G  1900544  // wsc|g1:ns=18, ldp=2048  (KC=64)
#define OFF_2  4259840  // g2:    ns=16, ldp=1536  (KC=32)
#define OFF_O  5832704  // wout:  ns=16, ldp=160   (KC=32)

__device__ __forceinline__ float tanh_fast(float x) {
    float y; asm("tanh.approx.f32 %0, %1;" : "=f"(y) : "f"(x)); return y;
}
__device__ __forceinline__ float gru_out(float gr, float gz, float gn,
                                         float br, float bz, float bn) {
    float r  = 1.f / (1.f + __expf(-(gr + br)));
    float z  = 1.f / (1.f + __expf(-(gz + bz)));
    float nn = tanhf(gn + r * bn);
    return (1.f - z) * nn;
}
__device__ __forceinline__ void add4(float4& a, const float4 b) {
    a.x += b.x; a.y += b.y; a.z += b.z; a.w += b.w;
}

// ---------------- X functors ----------------
struct XDirect {
    const float* X; int ldx;
    __device__ __forceinline__ float4 load4(int n, int k) const {
        return *reinterpret_cast<const float4*>(X + (size_t)n * ldx + k);
    }
    __device__ __forceinline__ float load1(int n, int k) const {
        return X[(size_t)n * ldx + k];
    }
};
struct XPre1Red {   // t1 = relu(pb1 + sum of 2 pre1 partials)
    const float* P1; const float* pb1;
    __device__ __forceinline__ float4 load4(int n, int k) const {
        float4 s = *reinterpret_cast<const float4*>(pb1 + k);
#pragma unroll
        for (int sp = 0; sp < 2; sp++)
            add4(s, *reinterpret_cast<const float4*>(P1 + sp * 32768 + n * 512 + k));
        s.x = fmaxf(s.x, 0.f); s.y = fmaxf(s.y, 0.f);
        s.z = fmaxf(s.z, 0.f); s.w = fmaxf(s.w, 0.f);
        return s;
    }
    __device__ __forceinline__ float load1(int n, int k) const {
        float s = pb1[k];
        for (int sp = 0; sp < 2; sp++) s += P1[sp * 32768 + n * 512 + k];
        return fmaxf(s, 0.f);
    }
};
struct XGru2Red {   // res2 = res1 + gru2 from 16 partials (ldp=1536)
    const float* P; const float* bih; const float* bhh; const float* res1;
    __device__ __forceinline__ float4 load4(int n, int k) const {
        const float* b = P + (size_t)n * 1536 + k;
        float4 r = *reinterpret_cast<const float4*>(bih + k);
        float4 z = *reinterpret_cast<const float4*>(bih + 512 + k);
        float4 m = *reinterpret_cast<const float4*>(bih + 1024 + k);
#pragma unroll
        for (int sp = 0; sp < 16; sp++) {
            const float* q = b + (size_t)sp * 98304;
            add4(r, *reinterpret_cast<const float4*>(q));
            add4(z, *reinterpret_cast<const float4*>(q + 512));
            add4(m, *reinterpret_cast<const float4*>(q + 1024));
        }
        float4 br = *reinterpret_cast<const float4*>(bhh + k);
        float4 bz = *reinterpret_cast<const float4*>(bhh + 512 + k);
        float4 bn = *reinterpret_cast<const float4*>(bhh + 1024 + k);
        float4 rv = *reinterpret_cast<const float4*>(res1 + n * 512 + k);
        float4 o;
        o.x = gru_out(r.x, z.x, m.x, br.x, bz.x, bn.x) + rv.x;
        o.y = gru_out(r.y, z.y, m.y, br.y, bz.y, bn.y) + rv.y;
        o.z = gru_out(r.z, z.z, m.z, br.z, bz.z, bn.z) + rv.z;
        o.w = gru_out(r.w, z.w, m.w, br.w, bz.w, bn.w) + rv.w;
        return o;
    }
    __device__ __forceinline__ float load1(int n, int k) const {
        float gr = bih[k], gz = bih[512 + k], gn = bih[1024 + k];
        for (int sp = 0; sp < 16; sp++) {
            const float* q = P + (size_t)sp * 98304 + (size_t)n * 1536 + k;
            gr += q[0]; gz += q[512]; gn += q[1024];
        }
        return gru_out(gr, gz, gn, bhh[k], bhh[512 + k], bhh[1024 + k]) + res1[n * 512 + k];
    }
};

// ---------------- k-split GEMM: 256 threads, tile 64j x 64n, thread 4j x 4n ----------------
struct GW {
    const float* W1; int m1; const float* W2; int ldw;
    int kjump_at, kjump_ofs, M, K, jt_n;
    float* P; int ldp;
};

template <int KC, class XF>
__global__ __launch_bounds__(256) void k_gemm(const XF xf, const GW g)
{
    constexpr int K4 = KC / 4;
    extern __shared__ float smem_[];
    float* xs = smem_;             // [KC][68]
    float* ws = smem_ + KC * 68;   // [KC][68]
    const int tid = threadIdx.x;
    const int it  = blockIdx.x;
    const int ksp = it / g.jt_n;
    const int jt  = it - ksp * g.jt_n;
    const int j0  = jt << 6;
    const int k0  = ksp * KC;

    for (int idx = tid; idx < K4 * 64; idx += 256) {
        int k4 = idx & (K4 - 1), n = idx / K4;
        int kk = k0 + (k4 << 2);
        float4 v = make_float4(0.f, 0.f, 0.f, 0.f);
        if (kk + 3 < g.K) v = xf.load4(n, kk);
        else {
            if (kk + 0 < g.K) v.x = xf.load1(n, kk + 0);
            if (kk + 1 < g.K) v.y = xf.load1(n, kk + 1);
            if (kk + 2 < g.K) v.z = xf.load1(n, kk + 2);
            if (kk + 3 < g.K) v.w = xf.load1(n, kk + 3);
        }
        float* d = xs + (k4 << 2) * 68 + n;
        d[0] = v.x; d[68] = v.y; d[136] = v.z; d[204] = v.w;
    }
    const int wofs = k0 + (k0 >= g.kjump_at ? g.kjump_ofs : 0);
    for (int idx = tid; idx < K4 * 64; idx += 256) {
        int k4 = idx & (K4 - 1), j = idx / K4;
        int jr = j0 + j;
        float4 v = make_float4(0.f, 0.f, 0.f, 0.f);
        if (jr < g.M) {
            const float* Wr = (jr < g.m1) ? (g.W1 + (size_t)jr * g.ldw)
                                          : (g.W2 + (size_t)(jr - g.m1) * g.ldw);
            int kk = k0 + (k4 << 2);
            if (kk + 3 < g.K) v = *reinterpret_cast<const float4*>(Wr + wofs + (k4 << 2));
            else {
                if (kk + 0 < g.K) v.x = Wr[wofs + (k4 << 2) + 0];
                if (kk + 1 < g.K) v.y = Wr[wofs + (k4 << 2) + 1];
                if (kk + 2 < g.K) v.z = Wr[wofs + (k4 << 2) + 2];
                if (kk + 3 < g.K) v.w = Wr[wofs + (k4 << 2) + 3];
            }
        }
        float* d = ws + (k4 << 2) * 68 + j;
        d[0] = v.x; d[68] = v.y; d[136] = v.z; d[204] = v.w;
    }
    __syncthreads();

    const int tj = tid & 15, tn = tid >> 4;
    float acc[4][4];
#pragma unroll
    for (int a = 0; a < 4; a++)
#pragma unroll
        for (int b = 0; b < 4; b++) acc[a][b] = 0.f;

#pragma unroll 8
    for (int k = 0; k < KC; k++) {
        float4 wv = *reinterpret_cast<const float4*>(ws + k * 68 + tj * 4);
        float4 xv = *reinterpret_cast<const float4*>(xs + k * 68 + tn * 4);
        float xr[4] = {xv.x, xv.y, xv.z, xv.w};
        float wr[4] = {wv.x, wv.y, wv.z, wv.w};
#pragma unroll
        for (int jj = 0; jj < 4; jj++)
#pragma unroll
            for (int i = 0; i < 4; i++) acc[jj][i] += wr[jj] * xr[i];
    }

    if (j0 + tj * 4 < g.M) {
        float* base = g.P + (size_t)ksp * (64 * g.ldp) + j0 + tj * 4;
#pragma unroll
        for (int i = 0; i < 4; i++) {
            int n = tn * 4 + i;
            *reinterpret_cast<float4*>(base + (size_t)n * g.ldp) =
                make_float4(acc[0][i], acc[1][i], acc[2][i], acc[3][i]);
        }
    }
}

// ---------------- tiny reduce kernels ----------------
// xga = [relu(pb2 + sum8 P2) | sv]
__global__ __launch_bounds__(256) void k_xga(const float* __restrict__ pb2,
                                             const float* __restrict__ sv)
{
    int gid = blockIdx.x * 256 + threadIdx.x;      // 64*96 f4
    if (gid >= 6144) return;
    int n = gid / 96, c4 = gid - n * 96;
    int c = c4 << 2;
    float4 v;
    if (c < 256) {
        v = *reinterpret_cast<const float4*>(pb2 + c);
#pragma unroll
        for (int sp = 0; sp < 8; sp++)
            add4(v, *reinterpret_cast<const float4*>(g_P + OFF_P2 + sp * 16384 + n * 256 + c));
        v.x = fmaxf(v.x, 0.f); v.y = fmaxf(v.y, 0.f);
        v.z = fmaxf(v.z, 0.f); v.w = fmaxf(v.w, 0.f);
    } else {
        v = *reinterpret_cast<const float4*>(sv + n * 128 + (c - 256));
    }
    *reinterpret_cast<float4*>(g_xga + n * 384 + c) = v;
}

// oatt = gruA(sum12 PA)
__global__ __launch_bounds__(256) void k_oatt(const float* __restrict__ bih,
                                              const float* __restrict__ bhh)
{
    int gid = blockIdx.x * 256 + threadIdx.x;      // 64*128 f4
    if (gid >= 8192) return;
    int n = gid >> 7, c = (gid & 127) << 2;
    float4 r = *reinterpret_cast<const float4*>(bih + c);
    float4 z = *reinterpret_cast<const float4*>(bih + 512 + c);
    float4 m = *reinterpret_cast<const float4*>(bih + 1024 + c);
#pragma unroll
    for (int sp = 0; sp < 12; sp++) {
        const float* q = g_P + OFF_A + (size_t)sp * 98304 + (size_t)n * 1536 + c;
        add4(r, *reinterpret_cast<const float4*>(q));
        add4(z, *reinterpret_cast<const float4*>(q + 512));
        add4(m, *reinterpret_cast<const float4*>(q + 1024));
    }
    float4 br = *reinterpret_cast<const float4*>(bhh + c);
    float4 bz = *reinterpret_cast<const float4*>(bhh + 512 + c);
    float4 bn = *reinterpret_cast<const float4*>(bhh + 1024 + c);
    float4 o;
    o.x = gru_out(r.x, z.x, m.x, br.x, bz.x, bn.x);
    o.y = gru_out(r.y, z.y, m.y, br.y, bz.y, bn.y);
    o.z = gru_out(r.z, z.z, m.z, br.z, bz.z, bn.z);
    o.w = gru_out(r.w, z.w, m.w, br.w, bz.w, bn.w);
    *reinterpret_cast<float4*>(g_oatt + n * 512 + c) = o;
}

// attW = bdec + sum16 PW
__global__ __launch_bounds__(256) void k_attw(const float* __restrict__ bdec)
{
    int gid = blockIdx.x * 256 + threadIdx.x;      // 64*128 f4
    if (gid >= 8192) return;
    int n = gid >> 7, c = (gid & 127) << 2;
    float4 s = *reinterpret_cast<const float4*>(bdec + c);
#pragma unroll
    for (int sp = 0; sp < 16; sp++)
        add4(s, *reinterpret_cast<const float4*>(g_P + OFF_W + sp * 32768 + n * 512 + c));
    *reinterpret_cast<float4*>(g_attW + n * 512 + c) = s;
}

// odec = [attn_norm | oatt | sv]; also writes attn_applied to d_out
__global__ __launch_bounds__(256) void k_odec(const float* __restrict__ sv,
                                              float* __restrict__ out)
{
    int gid = blockIdx.x * 256 + threadIdx.x;      // 64*288 f4
    if (gid >= 18432) return;
    int n = gid / 288, c4 = gid - n * 288;
    int c = c4 << 2;
    float4 v;
    if (c < 512) {
        v = make_float4(0.f, 0.f, 0.f, 0.f);
        float w = 0.f;
#pragma unroll
        for (int sp = 0; sp < 8; sp++) {
            add4(v, *reinterpret_cast<const float4*>(g_part + (size_t)(n * 8 + sp) * 512 + c));
            w += g_wchunk[n * 8 + sp];
        }
        float inv = 1.f / fmaxf(w, 1e-12f);
        v.x *= inv; v.y *= inv; v.z *= inv; v.w *= inv;
        *reinterpret_cast<float4*>(out + 10240 + (size_t)n * 512 + c) = v;
    } else if (c < 1024) {
        v = *reinterpret_cast<const float4*>(g_oatt + n * 512 + (c - 512));
    } else {
        v = *reinterpret_cast<const float4*>(sv + n * 128 + (c - 1024));
    }
    *reinterpret_cast<float4*>(g_odec + n * 1152 + c) = v;
}

// res1 = bsc + sum18(sc) + gru1(sum18)
__global__ __launch_bounds__(256) void k_res1(const float* __restrict__ bsc,
                                              const float* __restrict__ bih,
                                              const float* __restrict__ bhh)
{
    int gid = blockIdx.x * 256 + threadIdx.x;      // 64*128 f4
    if (gid >= 8192) return;
    int n = gid >> 7, c = (gid & 127) << 2;
    float4 sc = *reinterpret_cast<const float4*>(bsc + c);
    float4 r  = *reinterpret_cast<const float4*>(bih + c);
    float4 z  = *reinterpret_cast<const float4*>(bih + 512 + c);
    float4 m  = *reinterpret_cast<const float4*>(bih + 1024 + c);
#pragma unroll
    for (int sp = 0; sp < 18; sp++) {
        const float* pp = g_P + OFF_G + (size_t)sp * 131072 + (size_t)n * 2048;
        add4(sc, *reinterpret_cast<const float4*>(pp + c));
        add4(r,  *reinterpret_cast<const float4*>(pp + 512 + c));
        add4(z,  *reinterpret_cast<const float4*>(pp + 1024 + c));
        add4(m,  *reinterpret_cast<const float4*>(pp + 1536 + c));
    }
    float4 br = *reinterpret_cast<const float4*>(bhh + c);
    float4 bz = *reinterpret_cast<const float4*>(bhh + 512 + c);
    float4 bn = *reinterpret_cast<const float4*>(bhh + 1024 + c);
    float4 o;
    o.x = sc.x + gru_out(r.x, z.x, m.x, br.x, bz.x, bn.x);
    o.y = sc.y + gru_out(r.y, z.y, m.y, br.y, bz.y, bn.y);
    o.z = sc.z + gru_out(r.z, z.z, m.z, br.z, bz.z, bn.z);
    o.w = sc.w + gru_out(r.w, z.w, m.w, br.w, bz.w, bn.w);
    *reinterpret_cast<float4*>(g_res1 + n * 512 + c) = o;
}

// ---------------- fused attention: scores -> smem -> weighted sums ----------------
// block = (n, 128-row chunk)
__global__ __launch_bounds__(256) void k_scoreattn(
    const float* __restrict__ encW, const float* __restrict__ enc,
    const float* __restrict__ wattn, const float* __restrict__ battn,
    const int* __restrict__ len)
{
    const int n = blockIdx.x >> 3, ch = blockIdx.x & 7;
    const int t0 = ch << 7;
    const int rows = min(128, len[n] - t0);
    const int tid = threadIdx.x, lane = tid & 31, w = tid >> 5;

    if (rows <= 0) {
        *reinterpret_cast<float2*>(g_part + (size_t)(n * 8 + ch) * 512 + tid * 2) =
            make_float2(0.f, 0.f);
        if (tid == 0) g_wchunk[n * 8 + ch] = 0.f;
        return;
    }

    __shared__ float aw[512], wv[512], we[128], wred[8];
    for (int c4 = tid; c4 < 128; c4 += 256) {
        int c = c4 << 2;
        *reinterpret_cast<float4*>(aw + c) = *reinterpret_cast<const float4*>(g_attW + n * 512 + c);
        *reinterpret_cast<float4*>(wv + c) = *reinterpret_cast<const float4*>(wattn + c);
    }
    __syncthreads();

    // phase A: scores (warp w handles rows w*16 .. w*16+15)
    const float bat = battn[0];
    const float* base = encW + ((size_t)(n << 10) + t0) * 512;
    float wsum = 0.f;
    const int r0 = w * 16;
    const int r1 = min(r0 + 16, rows);
    for (int rr = r0; rr < r1; rr += 2) {
        const bool ok1 = (rr + 1 < r1);
        const float* rp = base + (size_t)rr * 512;
        float s0 = 0.f, s1 = 0.f;
#pragma unroll
        for (int q = 0; q < 4; q++) {
            int c = lane * 4 + q * 128;
            float4 v0 = *reinterpret_cast<const float4*>(rp + c);
            float4 v1 = ok1 ? *reinterpret_cast<const float4*>(rp + 512 + c)
                            : make_float4(0.f, 0.f, 0.f, 0.f);
            float4 a = *reinterpret_cast<const float4*>(aw + c);
            float4 wq = *reinterpret_cast<const float4*>(wv + c);
            s0 += tanh_fast(v0.x + a.x) * wq.x + tanh_fast(v0.y + a.y) * wq.y
                + tanh_fast(v0.z + a.z) * wq.z + tanh_fast(v0.w + a.w) * wq.w;
            s1 += tanh_fast(v1.x + a.x) * wq.x + tanh_fast(v1.y + a.y) * wq.y
                + tanh_fast(v1.z + a.z) * wq.z + tanh_fast(v1.w + a.w) * wq.w;
        }
#pragma unroll
        for (int o = 16; o > 0; o >>= 1) {
            s0 += __shfl_xor_sync(0xffffffffu, s0, o);
            s1 += __shfl_xor_sync(0xffffffffu, s1, o);
        }
        if (lane == 0) {
            float w0 = __expf(s0 + bat);
            we[rr] = w0; wsum += w0;
            if (ok1) { float w1 = __expf(s1 + bat); we[rr + 1] = w1; wsum += w1; }
        }
    }
    if (lane == 0) wred[w] = wsum;
    __syncthreads();
    if (tid == 0) {
        float s = 0.f;
#pragma unroll
        for (int i = 0; i < 8; i++) s += wred[i];
        g_wchunk[n * 8 + ch] = s;
    }

    // phase B: weighted column sums (thread = 2 cols)
    {
        const float* eb = enc + ((size_t)(n << 10) + t0) * 512 + tid * 2;
        float2 acc = make_float2(0.f, 0.f);
        int r = 0;
        for (; r + 16 <= rows; r += 16) {
            float wq[16]; float2 vv[16];
#pragma unroll
            for (int i = 0; i < 16; i++) {
                wq[i] = we[r + i];
                vv[i] = *reinterpret_cast<const float2*>(eb + (size_t)(r + i) * 512);
            }
#pragma unroll
            for (int i = 0; i < 16; i++) {
                acc.x += wq[i] * vv[i].x;
                acc.y += wq[i] * vv[i].y;
            }
        }
        for (; r < rows; r++) {
            float wq = we[r];
            float2 v = *reinterpret_cast<const float2*>(eb + (size_t)r * 512);
            acc.x += wq * v.x; acc.y += wq * v.y;
        }
        *reinterpret_cast<float2*>(g_part + (size_t)(n * 8 + ch) * 512 + tid * 2) = acc;
    }
}

// ---------------- final output reduce ----------------
__global__ __launch_bounds__(256) void k_out(const float* __restrict__ bout,
                                             float* __restrict__ out)
{
    int gid = blockIdx.x * 256 + threadIdx.x;
    if (gid >= 10240) return;
    int n = gid / 160, j = gid - n * 160;
    float s = bout[j];
#pragma unroll
    for (int sp = 0; sp < 16; sp++) s += g_P[OFF_O + sp * 10240 + n * 160 + j];
    out[gid] = s;
}

// ---------------- host orchestration ----------------
extern "C" void kernel_launch(void* const* d_in, const int* in_sizes, int n_in,
                              void* d_out, int out_size)
{
    (void)n_in; (void)out_size;
    bool dictord = (in_sizes[4] == 64);
    int b = dictord ? 5 : 4;

    const float* enc   = (const float*)d_in[0];
    const float* encW  = (const float*)d_in[1];
    const float* dec   = (const float*)d_in[2];
    const float* sv    = (const float*)d_in[3];
    const int*   len   = (const int*)(dictord ? d_in[4] : d_in[28]);
    const float* pw1   = (const float*)d_in[b + 0];
    const float* pb1   = (const float*)d_in[b + 1];
    const float* pw2   = (const float*)d_in[b + 2];
    const float* pb2   = (const float*)d_in[b + 3];
    const float* wdec_ = (const float*)d_in[b + 4];
    const float* bdec  = (const float*)d_in[b + 5];
    const float* ga_ih = (const float*)d_in[b + 6];
    const float* ga_bih= (const float*)d_in[b + 8];
    const float* ga_bhh= (const float*)d_in[b + 9];
    const float* wattn = (const float*)d_in[b + 10];
    const float* battn = (const float*)d_in[b + 11];
    const float* wsc   = (const float*)d_in[b + 12];
    const float* bsc   = (const float*)d_in[b + 13];
    const float* g1_ih = (const float*)d_in[b + 14];
    const float* g1_bih= (const float*)d_in[b + 16];
    const float* g1_bhh= (const float*)d_in[b + 17];
    const float* g2_ih = (const float*)d_in[b + 18];
    const float* g2_bih= (const float*)d_in[b + 20];
    const float* g2_bhh= (const float*)d_in[b + 21];
    const float* wout_ = (const float*)d_in[b + 22];
    const float* bout  = (const float*)d_in[b + 23];
    float* out = (float*)d_out;

    float *P, *xga, *oatt, *odec, *res1;
    cudaGetSymbolAddress((void**)&P,    g_P);
    cudaGetSymbolAddress((void**)&xga,  g_xga);
    cudaGetSymbolAddress((void**)&oatt, g_oatt);
    cudaGetSymbolAddress((void**)&odec, g_odec);
    cudaGetSymbolAddress((void**)&res1, g_res1);

    static bool attr_set = false;
    if (!attr_set) {
        cudaFuncSetAttribute(k_gemm<32, XDirect>,  cudaFuncAttributeMaxDynamicSharedMemorySize, 17408);
        cudaFuncSetAttribute(k_gemm<32, XGru2Red>, cudaFuncAttributeMaxDynamicSharedMemorySize, 17408);
        cudaFuncSetAttribute(k_gemm<64, XDirect>,  cudaFuncAttributeMaxDynamicSharedMemorySize, 34816);
        cudaFuncSetAttribute(k_gemm<64, XPre1Red>, cudaFuncAttributeMaxDynamicSharedMemorySize, 34816);
        attr_set = true;
    }

    const int BIGJ = 1 << 30;

    // 1. pre1 partials (M=512, K=80, KC=64, jt=8, ks=2) -> 16 blocks
    k_gemm<64, XDirect><<<16, 256, 34816>>>(XDirect{dec, 80},
        GW{pw1, BIGJ, pw1, 80, BIGJ, 0, 512, 80, 8, P + OFF_P1, 512});
    // 2. pre2 partials (M=256, K=512, KC=64, jt=4, ks=8) -> 32 blocks
    k_gemm<64, XPre1Red><<<32, 256, 34816>>>(XPre1Red{P + OFF_P1, pb1},
        GW{pw2, BIGJ, pw2, 512, BIGJ, 0, 256, 512, 4, P + OFF_P2, 256});
    // 3. xga = [relu(pre2) | sv]
    k_xga<<<24, 256>>>(pb2, sv);
    // 4. gruA partials (M=1536, K=384, KC=32, jt=24, ks=12), W col jump at 256 -> 288 blocks
    k_gemm<32, XDirect><<<288, 256, 17408>>>(XDirect{xga, 384},
        GW{ga_ih, BIGJ, ga_ih, 896, 256, 512, 1536, 384, 24, P + OFF_A, 1536});
    // 5. oatt = gruA reduce
    k_oatt<<<32, 256>>>(ga_bih, ga_bhh);
    // 6. wdec partials (M=512, K=512, KC=32, jt=8, ks=16) -> 128 blocks
    k_gemm<32, XDirect><<<128, 256, 17408>>>(XDirect{oatt, 512},
        GW{wdec_, BIGJ, wdec_, 512, BIGJ, 0, 512, 512, 8, P + OFF_W, 512});
    // 7. attW materialize
    k_attw<<<32, 256>>>(bdec);
    // 8. fused attention (512 blocks)
    k_scoreattn<<<512, 256>>>(encW, enc, wattn, battn, len);
    // 9. odec materialize + attn output write
    k_odec<<<72, 256>>>(sv, out);
    // 10. fused wsc|g1 partials (M=2048, K=1152, KC=64, jt=32, ks=18) -> 576 blocks
    k_gemm<64, XDirect><<<576, 256, 34816>>>(XDirect{odec, 1152},
        GW{wsc, 512, g1_ih, 1152, BIGJ, 0, 2048, 1152, 32, P + OFF_G, 2048});
    // 11. res1 reduce
    k_res1<<<32, 256>>>(bsc, g1_bih, g1_bhh);
    // 12. g2 partials (M=1536, K=512, KC=32, jt=24, ks=16) -> 384 blocks
    k_gemm<32, XDirect><<<384, 256, 17408>>>(XDirect{res1, 512},
        GW{g2_ih, BIGJ, g2_ih, 512, BIGJ, 0, 1536, 512, 24, P + OFF_2, 1536});
    // 13. wout partials (M=160, K=512, KC=32, jt=3, ks=16); X = res1 + gru2 -> 48 blocks
    k_gemm<32, XGru2Red><<<48, 256, 17408>>>(XGru2Red{P + OFF_2, g2_bih, g2_bhh, res1},
        GW{wout_, BIGJ, wout_, 512, BIGJ, 0, 160, 512, 3, P + OFF_O, 160});
    // 14. output reduce (40 blocks)
    k_out<<<40, 256>>>(bout, out);
}